// round 1
// baseline (speedup 1.0000x reference)
#include <cuda_runtime.h>
#include <math.h>

#define BB 2
#define TT 2048
#define DD 512
#define HH 8
#define DH 64
#define MT (BB*TT)   // 4096

// ---- scratch (static device globals; no allocation) ----
__device__ float g_Q[MT*DD];
__device__ float g_K[MT*DD];
__device__ float g_V[MT*DD];
__device__ float g_G[MT*DD];
__device__ float g_R[MT*DD];
__device__ float g_Y[MT*DD];

// ============================================================
// fp32 tiled GEMM: C[M,N] = A[M,K] @ B[K,N], 64x64 tile, BK=16,
// 256 threads, 4x4 micro-tile per thread.
// ============================================================
__global__ __launch_bounds__(256) void gemm64(const float* __restrict__ A,
                                              const float* __restrict__ Bm,
                                              float* __restrict__ C,
                                              int M, int N, int K) {
    __shared__ float As[16][65];   // [k][m] (transposed)
    __shared__ float Bs[16][68];   // [k][n], pad keeps float4 alignment

    int bm = blockIdx.y * 64;
    int bn = blockIdx.x * 64;
    int tid = threadIdx.x;
    int ty = tid >> 4;        // 0..15
    int tx = tid & 15;        // 0..15

    int a_m  = tid >> 2;          // 0..63
    int a_k4 = (tid & 3) * 4;     // 0,4,8,12
    int b_k  = tid >> 4;          // 0..15
    int b_n4 = (tid & 15) * 4;    // 0..60

    float acc[4][4];
    #pragma unroll
    for (int i = 0; i < 4; i++)
        #pragma unroll
        for (int j = 0; j < 4; j++) acc[i][j] = 0.f;

    for (int k0 = 0; k0 < K; k0 += 16) {
        float4 av = *(const float4*)&A[(size_t)(bm + a_m) * K + k0 + a_k4];
        As[a_k4 + 0][a_m] = av.x;
        As[a_k4 + 1][a_m] = av.y;
        As[a_k4 + 2][a_m] = av.z;
        As[a_k4 + 3][a_m] = av.w;
        float4 bv = *(const float4*)&Bm[(size_t)(k0 + b_k) * N + bn + b_n4];
        *(float4*)&Bs[b_k][b_n4] = bv;
        __syncthreads();

        #pragma unroll
        for (int kk = 0; kk < 16; kk++) {
            float a[4], b[4];
            #pragma unroll
            for (int i = 0; i < 4; i++) a[i] = As[kk][ty * 4 + i];
            #pragma unroll
            for (int j = 0; j < 4; j++) b[j] = Bs[kk][tx * 4 + j];
            #pragma unroll
            for (int i = 0; i < 4; i++)
                #pragma unroll
                for (int j = 0; j < 4; j++) acc[i][j] += a[i] * b[j];
        }
        __syncthreads();
    }

    #pragma unroll
    for (int i = 0; i < 4; i++) {
        float4 v = make_float4(acc[i][0], acc[i][1], acc[i][2], acc[i][3]);
        *(float4*)&C[(size_t)(bm + ty * 4 + i) * N + bn + tx * 4] = v;
    }
}

// ============================================================
// Retention: for one (b, h, query-tile of 64 tokens):
//   S = (Q K^T) * 0.125 * gamma^(n-m)  (causal), O = S V
// Causal structure: only key tiles kt <= qt contribute.
// ============================================================
#define RPAD 65
#define VPAD 68
#define SMEM_RET ((64*RPAD*3 + 64*VPAD) * 4)

__global__ __launch_bounds__(256) void retention_kernel(const float* __restrict__ Q,
                                                        const float* __restrict__ K,
                                                        const float* __restrict__ V,
                                                        float* __restrict__ O) {
    int qt = blockIdx.x;   // 0..31
    int h  = blockIdx.y;   // 0..7
    int b  = blockIdx.z;   // 0..1

    extern __shared__ float sm[];
    float* Qs = sm;                       // [d][i]  (64 x RPAD)
    float* Ks = sm + 64 * RPAD;           // [d][j]
    float* Ss = sm + 2 * 64 * RPAD;       // [m][i]
    float* Vs = sm + 3 * 64 * RPAD;       // [m][j]  (64 x VPAD)

    int tid = threadIdx.x;
    int ty = tid >> 4;    // 0..15
    int tx = tid & 15;    // 0..15

    float gamma = 1.f - exp2f(-5.f - (float)h);
    float logg  = logf(gamma);

    int r  = tid >> 4;          // 0..15 (row group for tile loads)
    int c4 = (tid & 15) * 4;    // 0..60

    // load Q tile transposed: Qs[d][i]
    const float* Qb = Q + ((size_t)b * TT + qt * 64) * DD + h * DH;
    #pragma unroll
    for (int rr = r; rr < 64; rr += 16) {
        float4 v = *(const float4*)&Qb[(size_t)rr * DD + c4];
        Qs[(c4 + 0) * RPAD + rr] = v.x;
        Qs[(c4 + 1) * RPAD + rr] = v.y;
        Qs[(c4 + 2) * RPAD + rr] = v.z;
        Qs[(c4 + 3) * RPAD + rr] = v.w;
    }

    float o[4][4];
    #pragma unroll
    for (int i = 0; i < 4; i++)
        #pragma unroll
        for (int j = 0; j < 4; j++) o[i][j] = 0.f;

    for (int kt = 0; kt <= qt; kt++) {
        // load K tile transposed, V tile direct
        const float* Kb = K + ((size_t)b * TT + kt * 64) * DD + h * DH;
        const float* Vb = V + ((size_t)b * TT + kt * 64) * DD + h * DH;
        #pragma unroll
        for (int rr = r; rr < 64; rr += 16) {
            float4 kv = *(const float4*)&Kb[(size_t)rr * DD + c4];
            Ks[(c4 + 0) * RPAD + rr] = kv.x;
            Ks[(c4 + 1) * RPAD + rr] = kv.y;
            Ks[(c4 + 2) * RPAD + rr] = kv.z;
            Ks[(c4 + 3) * RPAD + rr] = kv.w;
            float4 vv = *(const float4*)&Vb[(size_t)rr * DD + c4];
            *(float4*)&Vs[rr * VPAD + c4] = vv;
        }
        __syncthreads();

        // S tile: s[i][j] = sum_d Qs[d][i]*Ks[d][j]
        float s[4][4];
        #pragma unroll
        for (int i = 0; i < 4; i++)
            #pragma unroll
            for (int j = 0; j < 4; j++) s[i][j] = 0.f;
        #pragma unroll 8
        for (int d = 0; d < 64; d++) {
            float a[4], bv[4];
            #pragma unroll
            for (int i = 0; i < 4; i++) a[i] = Qs[d * RPAD + ty * 4 + i];
            #pragma unroll
            for (int j = 0; j < 4; j++) bv[j] = Ks[d * RPAD + tx * 4 + j];
            #pragma unroll
            for (int i = 0; i < 4; i++)
                #pragma unroll
                for (int j = 0; j < 4; j++) s[i][j] += a[i] * bv[j];
        }

        // decay weights + store S transposed: Ss[m][i]
        int base_diff = (qt - kt) * 64;
        #pragma unroll
        for (int i = 0; i < 4; i++) {
            #pragma unroll
            for (int j = 0; j < 4; j++) {
                int diff = base_diff + (ty * 4 + i) - (tx * 4 + j);
                float w = (diff >= 0) ? 0.125f * expf((float)diff * logg) : 0.f;
                Ss[(tx * 4 + j) * RPAD + ty * 4 + i] = s[i][j] * w;
            }
        }
        __syncthreads();

        // O += S V : o[i][j] += sum_m Ss[m][i] * Vs[m][j]
        #pragma unroll 8
        for (int m = 0; m < 64; m++) {
            float a[4], bv[4];
            #pragma unroll
            for (int i = 0; i < 4; i++) a[i] = Ss[m * RPAD + ty * 4 + i];
            #pragma unroll
            for (int j = 0; j < 4; j++) bv[j] = Vs[m * VPAD + tx * 4 + j];
            #pragma unroll
            for (int i = 0; i < 4; i++)
                #pragma unroll
                for (int j = 0; j < 4; j++) o[i][j] += a[i] * bv[j];
        }
        __syncthreads();
    }

    // write O
    float* Ob = O + ((size_t)b * TT + qt * 64) * DD + h * DH;
    #pragma unroll
    for (int i = 0; i < 4; i++) {
        float4 v = make_float4(o[i][0], o[i][1], o[i][2], o[i][3]);
        *(float4*)&Ob[(size_t)(ty * 4 + i) * DD + tx * 4] = v;
    }
}

// ============================================================
// GroupNorm (8 groups of 64) + SiLU gate:
//   Y = silu(G + GN(R))
// 1 block per token, 1 warp per group, 2 elements per lane.
// ============================================================
__global__ __launch_bounds__(256) void gn_gate(const float* __restrict__ R,
                                               const float* __restrict__ G,
                                               const float* __restrict__ w,
                                               const float* __restrict__ bias,
                                               float* __restrict__ Y) {
    int token = blockIdx.x;
    int warp  = threadIdx.x >> 5;   // group = head
    int lane  = threadIdx.x & 31;

    const float* r = R + (size_t)token * DD + warp * DH;
    float v0 = r[lane];
    float v1 = r[lane + 32];
    float s  = v0 + v1;
    float sq = v0 * v0 + v1 * v1;
    #pragma unroll
    for (int off = 16; off > 0; off >>= 1) {
        s  += __shfl_xor_sync(0xffffffffu, s,  off);
        sq += __shfl_xor_sync(0xffffffffu, sq, off);
    }
    float mean = s * (1.f / 64.f);
    float var  = sq * (1.f / 64.f) - mean * mean;
    float inv  = rsqrtf(var + 1e-5f);

    int c0 = warp * DH + lane;
    float n0 = (v0 - mean) * inv * w[c0]      + bias[c0];
    float n1 = (v1 - mean) * inv * w[c0 + 32] + bias[c0 + 32];

    const float* g = G + (size_t)token * DD;
    float z0 = g[c0] + n0;
    float z1 = g[c0 + 32] + n1;
    Y[(size_t)token * DD + c0]      = z0 / (1.f + expf(-z0));
    Y[(size_t)token * DD + c0 + 32] = z1 / (1.f + expf(-z1));
}

// ============================================================
extern "C" void kernel_launch(void* const* d_in, const int* in_sizes, int n_in,
                              void* d_out, int out_size) {
    const float* x   = (const float*)d_in[0];
    const float* WQ  = (const float*)d_in[1];
    const float* WK  = (const float*)d_in[2];
    const float* WV  = (const float*)d_in[3];
    const float* WG  = (const float*)d_in[4];
    const float* WO  = (const float*)d_in[5];
    const float* gnw = (const float*)d_in[6];
    const float* gnb = (const float*)d_in[7];
    float* out = (float*)d_out;

    float *Qp, *Kp, *Vp, *Gp, *Rp, *Yp;
    cudaGetSymbolAddress((void**)&Qp, g_Q);
    cudaGetSymbolAddress((void**)&Kp, g_K);
    cudaGetSymbolAddress((void**)&Vp, g_V);
    cudaGetSymbolAddress((void**)&Gp, g_G);
    cudaGetSymbolAddress((void**)&Rp, g_R);
    cudaGetSymbolAddress((void**)&Yp, g_Y);

    cudaFuncSetAttribute(retention_kernel,
                         cudaFuncAttributeMaxDynamicSharedMemorySize, SMEM_RET);

    dim3 gproj(DD / 64, MT / 64);  // (8, 64)

    gemm64<<<gproj, 256>>>(x, WQ, Qp, MT, DD, DD);
    gemm64<<<gproj, 256>>>(x, WK, Kp, MT, DD, DD);
    gemm64<<<gproj, 256>>>(x, WV, Vp, MT, DD, DD);
    gemm64<<<gproj, 256>>>(x, WG, Gp, MT, DD, DD);

    retention_kernel<<<dim3(TT / 64, HH, BB), 256, SMEM_RET>>>(Qp, Kp, Vp, Rp);

    gn_gate<<<MT, 256>>>(Rp, Gp, gnw, gnb, Yp);

    gemm64<<<gproj, 256>>>(Yp, WO, out, MT, DD, DD);
}

// round 3
// speedup vs baseline: 2.6027x; 2.6027x over previous
#include <cuda_runtime.h>
#include <math.h>

#define BB 2
#define TT 2048
#define DD 512
#define HH 8
#define DH 64
#define MT (BB*TT)   // 4096

// ---- scratch (static device globals; no allocation) ----
__device__ float g_Q[MT*DD];
__device__ float g_K[MT*DD];
__device__ float g_V[MT*DD];
__device__ float g_G[MT*DD];
__device__ float g_R[MT*DD];
__device__ float g_Y[MT*DD];

// ---- tf32 helpers ----
__device__ __forceinline__ float f2tf(float x) {
    unsigned u;
    asm("cvt.rna.tf32.f32 %0, %1;" : "=r"(u) : "f"(x));
    return __uint_as_float(u);
}

__device__ __forceinline__ void mma8(float* c, const unsigned* a, const unsigned* b) {
    asm volatile("mma.sync.aligned.m16n8k8.row.col.f32.tf32.tf32.f32 "
        "{%0,%1,%2,%3}, {%4,%5,%6,%7}, {%8,%9}, {%0,%1,%2,%3};\n"
        : "+f"(c[0]), "+f"(c[1]), "+f"(c[2]), "+f"(c[3])
        : "r"(a[0]), "r"(a[1]), "r"(a[2]), "r"(a[3]), "r"(b[0]), "r"(b[1]));
}

// ============================================================
// tf32 GEMM body: C[M,N] = A[M,K] @ B[K,N]
// block tile 128x128, ktile 16, 256 threads = 8 warps (4M x 2N),
// warp tile 32x64 -> 2 mtiles x 8 ntiles of m16n8k8.
// ============================================================
__device__ __forceinline__ void gemm_body(const float* __restrict__ A,
                                          const float* __restrict__ B,
                                          float* __restrict__ C,
                                          int M, int N, int K)
{
    __shared__ float As[128][20];    // [m][k], stride 20 -> conflict-free A frags
    __shared__ float Bs[16][136];    // [k][n], stride 136 -> conflict-free B frags

    int tid = threadIdx.x;
    int w = tid >> 5, lane = tid & 31;
    int g = lane >> 2, t = lane & 3;
    int wm = (w >> 1) * 32;          // 0,32,64,96
    int wn = (w & 1) * 64;           // 0,64
    int bm = blockIdx.y * 128, bn = blockIdx.x * 128;

    int am = tid >> 2, ak = (tid & 3) * 4;     // A tile: rows am, am+64
    int bk = tid >> 5, bn4 = (tid & 31) * 4;   // B tile: rows bk, bk+8

    float acc[2][8][4];
    #pragma unroll
    for (int i = 0; i < 2; i++)
        #pragma unroll
        for (int j = 0; j < 8; j++)
            #pragma unroll
            for (int q = 0; q < 4; q++) acc[i][j][q] = 0.f;

    const float* Arow0 = A + (size_t)(bm + am) * K + ak;
    const float* Arow1 = A + (size_t)(bm + am + 64) * K + ak;
    const float* Bbase = B + (size_t)bk * N + bn + bn4;

    float4 pa0 = *(const float4*)(Arow0);
    float4 pa1 = *(const float4*)(Arow1);
    float4 pb0 = *(const float4*)(Bbase);
    float4 pb1 = *(const float4*)(Bbase + (size_t)8 * N);

    int ntile = K >> 4;
    for (int kt = 0; kt < ntile; kt++) {
        // store current tile (tf32-converted)
        As[am][ak+0] = f2tf(pa0.x); As[am][ak+1] = f2tf(pa0.y);
        As[am][ak+2] = f2tf(pa0.z); As[am][ak+3] = f2tf(pa0.w);
        As[am+64][ak+0] = f2tf(pa1.x); As[am+64][ak+1] = f2tf(pa1.y);
        As[am+64][ak+2] = f2tf(pa1.z); As[am+64][ak+3] = f2tf(pa1.w);
        Bs[bk][bn4+0] = f2tf(pb0.x); Bs[bk][bn4+1] = f2tf(pb0.y);
        Bs[bk][bn4+2] = f2tf(pb0.z); Bs[bk][bn4+3] = f2tf(pb0.w);
        Bs[bk+8][bn4+0] = f2tf(pb1.x); Bs[bk+8][bn4+1] = f2tf(pb1.y);
        Bs[bk+8][bn4+2] = f2tf(pb1.z); Bs[bk+8][bn4+3] = f2tf(pb1.w);
        __syncthreads();

        // prefetch next tile into registers
        if (kt + 1 < ntile) {
            int off = (kt + 1) * 16;
            pa0 = *(const float4*)(Arow0 + off);
            pa1 = *(const float4*)(Arow1 + off);
            pb0 = *(const float4*)(Bbase + (size_t)off * N);
            pb1 = *(const float4*)(Bbase + (size_t)(off + 8) * N);
        }

        // compute 2 x k8 sub-steps
        #pragma unroll
        for (int ks = 0; ks < 2; ks++) {
            int k0 = ks * 8;
            unsigned a[2][4], bf[8][2];
            #pragma unroll
            for (int mt = 0; mt < 2; mt++) {
                int r = wm + mt * 16;
                a[mt][0] = __float_as_uint(As[r + g][k0 + t]);
                a[mt][1] = __float_as_uint(As[r + 8 + g][k0 + t]);
                a[mt][2] = __float_as_uint(As[r + g][k0 + t + 4]);
                a[mt][3] = __float_as_uint(As[r + 8 + g][k0 + t + 4]);
            }
            #pragma unroll
            for (int nt = 0; nt < 8; nt++) {
                int c = wn + nt * 8 + g;
                bf[nt][0] = __float_as_uint(Bs[k0 + t][c]);
                bf[nt][1] = __float_as_uint(Bs[k0 + t + 4][c]);
            }
            #pragma unroll
            for (int mt = 0; mt < 2; mt++)
                #pragma unroll
                for (int nt = 0; nt < 8; nt++)
                    mma8(acc[mt][nt], a[mt], bf[nt]);
        }
        __syncthreads();
    }

    // epilogue
    #pragma unroll
    for (int mt = 0; mt < 2; mt++)
        #pragma unroll
        for (int nt = 0; nt < 8; nt++) {
            int r = bm + wm + mt * 16 + g;
            int c = bn + wn + nt * 8 + 2 * t;
            *(float2*)&C[(size_t)r * N + c] = make_float2(acc[mt][nt][0], acc[mt][nt][1]);
            *(float2*)&C[(size_t)(r + 8) * N + c] = make_float2(acc[mt][nt][2], acc[mt][nt][3]);
        }
}

// fused 4-way projection: z selects weight/output
__global__ __launch_bounds__(256) void proj4_kernel(const float* __restrict__ x,
    const float* __restrict__ WQ, const float* __restrict__ WK,
    const float* __restrict__ WV, const float* __restrict__ WG,
    float* Qo, float* Ko, float* Vo, float* Go)
{
    const float* Bp; float* Cp;
    switch (blockIdx.z) {
        case 0:  Bp = WQ; Cp = Qo; break;
        case 1:  Bp = WK; Cp = Ko; break;
        case 2:  Bp = WV; Cp = Vo; break;
        default: Bp = WG; Cp = Go; break;
    }
    gemm_body(x, Bp, Cp, MT, DD, DD);
}

__global__ __launch_bounds__(256) void gemm_kernel(const float* __restrict__ A,
                                                   const float* __restrict__ B,
                                                   float* __restrict__ C)
{
    gemm_body(A, B, C, MT, DD, DD);
}

// ============================================================
// Retention via tf32 mma: per (qtile64, h, b) block.
// S = (0.125 Q) K^T, weighted by gamma^(n-m) causal, O = S V.
// 8 warps as 2x4: warp S/O tile 32x16.
// ============================================================
#define QSTR 68   // [row][col] stride for Qs/Ss (A operands): (4g+t)%32 distinct
#define KSTR 72   // [k][n] stride for Ks/Vs (B operands): (8t+g)%32 distinct
#define RET_SMEM ((64*QSTR*2 + 64*KSTR*2)*4)

__global__ __launch_bounds__(256) void retention_mma(const float* __restrict__ Q,
    const float* __restrict__ K, const float* __restrict__ V, float* __restrict__ O)
{
    extern __shared__ float sm[];
    float* Qs = sm;                       // [i][d]  64 x QSTR
    float* Ss = Qs + 64 * QSTR;           // [i][m]  64 x QSTR
    float* Ks = Ss + 64 * QSTR;           // [d][j]  64 x KSTR
    float* Vs = Ks + 64 * KSTR;           // [m][d]  64 x KSTR

    int qt = blockIdx.x, h = blockIdx.y, b = blockIdx.z;
    int tid = threadIdx.x;
    int w = tid >> 5, lane = tid & 31;
    int g = lane >> 2, t = lane & 3;
    int wi = (w >> 2) * 32;   // 0,32
    int wj = (w & 3) * 16;    // 0,16,32,48

    float log2g = log2f(1.f - exp2f(-5.f - (float)h));

    int lr = tid >> 2, lc = (tid & 3) * 4;

    // load Q tile (scaled by 1/8, tf32)
    const float* Qb = Q + ((size_t)b * TT + (size_t)qt * 64) * DD + h * DH;
    #pragma unroll
    for (int p = 0; p < 4; p++) {
        int c0 = lc + p * 16;
        float4 v = *(const float4*)&Qb[(size_t)lr * DD + c0];
        Qs[lr * QSTR + c0 + 0] = f2tf(0.125f * v.x);
        Qs[lr * QSTR + c0 + 1] = f2tf(0.125f * v.y);
        Qs[lr * QSTR + c0 + 2] = f2tf(0.125f * v.z);
        Qs[lr * QSTR + c0 + 3] = f2tf(0.125f * v.w);
    }

    float oacc[2][2][4];
    #pragma unroll
    for (int i = 0; i < 2; i++)
        #pragma unroll
        for (int j = 0; j < 2; j++)
            #pragma unroll
            for (int q = 0; q < 4; q++) oacc[i][j][q] = 0.f;

    for (int kt = 0; kt <= qt; kt++) {
        __syncthreads();  // prior readers of Ks/Vs/Ss done; also orders Qs writes (kt=0)

        const float* Kb = K + ((size_t)b * TT + (size_t)kt * 64) * DD + h * DH;
        const float* Vb = V + ((size_t)b * TT + (size_t)kt * 64) * DD + h * DH;
        #pragma unroll
        for (int p = 0; p < 4; p++) {
            int c0 = lc + p * 16;
            float4 kv = *(const float4*)&Kb[(size_t)lr * DD + c0];
            Ks[(c0 + 0) * KSTR + lr] = f2tf(kv.x);
            Ks[(c0 + 1) * KSTR + lr] = f2tf(kv.y);
            Ks[(c0 + 2) * KSTR + lr] = f2tf(kv.z);
            Ks[(c0 + 3) * KSTR + lr] = f2tf(kv.w);
            float4 vv = *(const float4*)&Vb[(size_t)lr * DD + c0];
            Vs[lr * KSTR + c0 + 0] = f2tf(vv.x);
            Vs[lr * KSTR + c0 + 1] = f2tf(vv.y);
            Vs[lr * KSTR + c0 + 2] = f2tf(vv.z);
            Vs[lr * KSTR + c0 + 3] = f2tf(vv.w);
        }
        __syncthreads();

        // S = Q K^T for this warp's 32x16 region
        float sacc[2][2][4];
        #pragma unroll
        for (int i = 0; i < 2; i++)
            #pragma unroll
            for (int j = 0; j < 2; j++)
                #pragma unroll
                for (int q = 0; q < 4; q++) sacc[i][j][q] = 0.f;

        #pragma unroll
        for (int d8 = 0; d8 < 8; d8++) {
            int k0 = d8 * 8;
            unsigned a[2][4], bf[2][2];
            #pragma unroll
            for (int mt = 0; mt < 2; mt++) {
                int r = wi + mt * 16;
                a[mt][0] = __float_as_uint(Qs[(r + g) * QSTR + k0 + t]);
                a[mt][1] = __float_as_uint(Qs[(r + 8 + g) * QSTR + k0 + t]);
                a[mt][2] = __float_as_uint(Qs[(r + g) * QSTR + k0 + t + 4]);
                a[mt][3] = __float_as_uint(Qs[(r + 8 + g) * QSTR + k0 + t + 4]);
            }
            #pragma unroll
            for (int nt = 0; nt < 2; nt++) {
                int c = wj + nt * 8 + g;
                bf[nt][0] = __float_as_uint(Ks[(k0 + t) * KSTR + c]);
                bf[nt][1] = __float_as_uint(Ks[(k0 + t + 4) * KSTR + c]);
            }
            #pragma unroll
            for (int mt = 0; mt < 2; mt++)
                #pragma unroll
                for (int nt = 0; nt < 2; nt++)
                    mma8(sacc[mt][nt], a[mt], bf[nt]);
        }

        // decay weights + store S (as A operand layout [i][m]) in tf32
        int base = (qt - kt) * 64;
        #pragma unroll
        for (int mt = 0; mt < 2; mt++) {
            #pragma unroll
            for (int nt = 0; nt < 2; nt++) {
                int r0 = wi + mt * 16 + g;
                int c0 = wj + nt * 8 + 2 * t;
                #pragma unroll
                for (int e = 0; e < 4; e++) {
                    int r = r0 + (e >> 1) * 8;
                    int c = c0 + (e & 1);
                    int diff = base + r - c;
                    float wgt = (diff >= 0) ? exp2f((float)diff * log2g) : 0.f;
                    Ss[r * QSTR + c] = f2tf(sacc[mt][nt][e] * wgt);
                }
            }
        }
        __syncthreads();

        // O += S V for this warp's 32x16 region
        #pragma unroll
        for (int m8 = 0; m8 < 8; m8++) {
            int k0 = m8 * 8;
            unsigned a[2][4], bf[2][2];
            #pragma unroll
            for (int mt = 0; mt < 2; mt++) {
                int r = wi + mt * 16;
                a[mt][0] = __float_as_uint(Ss[(r + g) * QSTR + k0 + t]);
                a[mt][1] = __float_as_uint(Ss[(r + 8 + g) * QSTR + k0 + t]);
                a[mt][2] = __float_as_uint(Ss[(r + g) * QSTR + k0 + t + 4]);
                a[mt][3] = __float_as_uint(Ss[(r + 8 + g) * QSTR + k0 + t + 4]);
            }
            #pragma unroll
            for (int nt = 0; nt < 2; nt++) {
                int c = wj + nt * 8 + g;
                bf[nt][0] = __float_as_uint(Vs[(k0 + t) * KSTR + c]);
                bf[nt][1] = __float_as_uint(Vs[(k0 + t + 4) * KSTR + c]);
            }
            #pragma unroll
            for (int mt = 0; mt < 2; mt++)
                #pragma unroll
                for (int nt = 0; nt < 2; nt++)
                    mma8(oacc[mt][nt], a[mt], bf[nt]);
        }
    }

    // write O
    float* Ob = O + ((size_t)b * TT + (size_t)qt * 64) * DD + h * DH;
    #pragma unroll
    for (int mt = 0; mt < 2; mt++)
        #pragma unroll
        for (int nt = 0; nt < 2; nt++) {
            int r = wi + mt * 16 + g;
            int c = wj + nt * 8 + 2 * t;
            *(float2*)&Ob[(size_t)r * DD + c] = make_float2(oacc[mt][nt][0], oacc[mt][nt][1]);
            *(float2*)&Ob[(size_t)(r + 8) * DD + c] = make_float2(oacc[mt][nt][2], oacc[mt][nt][3]);
        }
}

// ============================================================
// GroupNorm (8 groups of 64) + SiLU gate: Y = silu(G + GN(R))
// ============================================================
__global__ __launch_bounds__(256) void gn_gate(const float* __restrict__ R,
                                               const float* __restrict__ G,
                                               const float* __restrict__ w,
                                               const float* __restrict__ bias,
                                               float* __restrict__ Y) {
    int token = blockIdx.x;
    int warp  = threadIdx.x >> 5;
    int lane  = threadIdx.x & 31;

    const float* r = R + (size_t)token * DD + warp * DH;
    float v0 = r[lane];
    float v1 = r[lane + 32];
    float s  = v0 + v1;
    float sq = v0 * v0 + v1 * v1;
    #pragma unroll
    for (int off = 16; off > 0; off >>= 1) {
        s  += __shfl_xor_sync(0xffffffffu, s,  off);
        sq += __shfl_xor_sync(0xffffffffu, sq, off);
    }
    float mean = s * (1.f / 64.f);
    float var  = sq * (1.f / 64.f) - mean * mean;
    float inv  = rsqrtf(var + 1e-5f);

    int c0 = warp * DH + lane;
    float n0 = (v0 - mean) * inv * w[c0]      + bias[c0];
    float n1 = (v1 - mean) * inv * w[c0 + 32] + bias[c0 + 32];

    const float* g = G + (size_t)token * DD;
    float z0 = g[c0] + n0;
    float z1 = g[c0 + 32] + n1;
    Y[(size_t)token * DD + c0]      = z0 / (1.f + expf(-z0));
    Y[(size_t)token * DD + c0 + 32] = z1 / (1.f + expf(-z1));
}

// ============================================================
extern "C" void kernel_launch(void* const* d_in, const int* in_sizes, int n_in,
                              void* d_out, int out_size) {
    const float* x   = (const float*)d_in[0];
    const float* WQ  = (const float*)d_in[1];
    const float* WK  = (const float*)d_in[2];
    const float* WV  = (const float*)d_in[3];
    const float* WG  = (const float*)d_in[4];
    const float* WO  = (const float*)d_in[5];
    const float* gnw = (const float*)d_in[6];
    const float* gnb = (const float*)d_in[7];
    float* out = (float*)d_out;

    float *Qp, *Kp, *Vp, *Gp, *Rp, *Yp;
    cudaGetSymbolAddress((void**)&Qp, g_Q);
    cudaGetSymbolAddress((void**)&Kp, g_K);
    cudaGetSymbolAddress((void**)&Vp, g_V);
    cudaGetSymbolAddress((void**)&Gp, g_G);
    cudaGetSymbolAddress((void**)&Rp, g_R);
    cudaGetSymbolAddress((void**)&Yp, g_Y);

    cudaFuncSetAttribute(retention_mma,
                         cudaFuncAttributeMaxDynamicSharedMemorySize, RET_SMEM);

    proj4_kernel<<<dim3(DD / 128, MT / 128, 4), 256>>>(x, WQ, WK, WV, WG,
                                                       Qp, Kp, Vp, Gp);

    retention_mma<<<dim3(TT / 64, HH, BB), 256, RET_SMEM>>>(Qp, Kp, Vp, Rp);

    gn_gate<<<MT, 256>>>(Rp, Gp, gnw, gnb, Yp);

    gemm_kernel<<<dim3(DD / 128, MT / 128, 1), 256>>>(Yp, WO, out);
}

// round 4
// speedup vs baseline: 5.6594x; 2.1744x over previous
#include <cuda_runtime.h>
#include <math.h>

#define BB 2
#define TT 2048
#define DD 512
#define HH 8
#define DH 64
#define MT (BB*TT)   // 4096
#define NC 32        // chunks per sequence
#define CS 64        // chunk size

// ---- scratch (static device globals; no allocation) ----
__device__ float g_Q[MT*DD];
__device__ float g_K[MT*DD];
__device__ float g_V[MT*DD];
__device__ float g_G[MT*DD];
__device__ float g_Y[MT*DD];
__device__ float g_B[BB*HH*NC*DH*DH];   // per-chunk outer products
__device__ float g_S[BB*HH*NC*DH*DH];   // scanned states

// ---- tf32 helpers ----
__device__ __forceinline__ float f2tf(float x) {
    unsigned u;
    asm("cvt.rna.tf32.f32 %0, %1;" : "=r"(u) : "f"(x));
    return __uint_as_float(u);
}

__device__ __forceinline__ void mma8(float* c, const unsigned* a, const unsigned* b) {
    asm volatile("mma.sync.aligned.m16n8k8.row.col.f32.tf32.tf32.f32 "
        "{%0,%1,%2,%3}, {%4,%5,%6,%7}, {%8,%9}, {%0,%1,%2,%3};\n"
        : "+f"(c[0]), "+f"(c[1]), "+f"(c[2]), "+f"(c[3])
        : "r"(a[0]), "r"(a[1]), "r"(a[2]), "r"(a[3]), "r"(b[0]), "r"(b[1]));
}

// ============================================================
// tf32 GEMM: C[M,N] = A[M,K] @ B[K,N], 128x128 tile, BK=16,
// 256 threads = 8 warps (4Mx2N), warp 32x64, DOUBLE-BUFFERED.
// ============================================================
__device__ __forceinline__ void gemm_body(const float* __restrict__ A,
                                          const float* __restrict__ B,
                                          float* __restrict__ C,
                                          int M, int N, int K)
{
    __shared__ float As[2][128][20];
    __shared__ float Bs[2][16][136];

    int tid = threadIdx.x;
    int w = tid >> 5, lane = tid & 31;
    int g = lane >> 2, t = lane & 3;
    int wm = (w >> 1) * 32;
    int wn = (w & 1) * 64;
    int bm = blockIdx.y * 128, bn = blockIdx.x * 128;

    int am = tid >> 2, ak = (tid & 3) * 4;
    int bk = tid >> 5, bn4 = (tid & 31) * 4;

    float acc[2][8][4];
    #pragma unroll
    for (int i = 0; i < 2; i++)
        #pragma unroll
        for (int j = 0; j < 8; j++)
            #pragma unroll
            for (int q = 0; q < 4; q++) acc[i][j][q] = 0.f;

    const float* Arow0 = A + (size_t)(bm + am) * K + ak;
    const float* Arow1 = Arow0 + (size_t)64 * K;
    const float* Bbase = B + (size_t)bk * N + bn + bn4;

    float4 pa0 = *(const float4*)(Arow0);
    float4 pa1 = *(const float4*)(Arow1);
    float4 pb0 = *(const float4*)(Bbase);
    float4 pb1 = *(const float4*)(Bbase + (size_t)8 * N);

    // store tile 0 into buffer 0
    As[0][am][ak+0] = f2tf(pa0.x); As[0][am][ak+1] = f2tf(pa0.y);
    As[0][am][ak+2] = f2tf(pa0.z); As[0][am][ak+3] = f2tf(pa0.w);
    As[0][am+64][ak+0] = f2tf(pa1.x); As[0][am+64][ak+1] = f2tf(pa1.y);
    As[0][am+64][ak+2] = f2tf(pa1.z); As[0][am+64][ak+3] = f2tf(pa1.w);
    Bs[0][bk][bn4+0] = f2tf(pb0.x); Bs[0][bk][bn4+1] = f2tf(pb0.y);
    Bs[0][bk][bn4+2] = f2tf(pb0.z); Bs[0][bk][bn4+3] = f2tf(pb0.w);
    Bs[0][bk+8][bn4+0] = f2tf(pb1.x); Bs[0][bk+8][bn4+1] = f2tf(pb1.y);
    Bs[0][bk+8][bn4+2] = f2tf(pb1.z); Bs[0][bk+8][bn4+3] = f2tf(pb1.w);
    __syncthreads();

    int ntile = K >> 4;
    for (int kt = 0; kt < ntile; kt++) {
        int cur = kt & 1, nxt = cur ^ 1;
        if (kt + 1 < ntile) {
            int off = (kt + 1) * 16;
            pa0 = *(const float4*)(Arow0 + off);
            pa1 = *(const float4*)(Arow1 + off);
            pb0 = *(const float4*)(Bbase + (size_t)off * N);
            pb1 = *(const float4*)(Bbase + (size_t)(off + 8) * N);
        }

        #pragma unroll
        for (int ks = 0; ks < 2; ks++) {
            int k0 = ks * 8;
            unsigned a[2][4], bf[8][2];
            #pragma unroll
            for (int mt = 0; mt < 2; mt++) {
                int r = wm + mt * 16;
                a[mt][0] = __float_as_uint(As[cur][r + g][k0 + t]);
                a[mt][1] = __float_as_uint(As[cur][r + 8 + g][k0 + t]);
                a[mt][2] = __float_as_uint(As[cur][r + g][k0 + t + 4]);
                a[mt][3] = __float_as_uint(As[cur][r + 8 + g][k0 + t + 4]);
            }
            #pragma unroll
            for (int nt = 0; nt < 8; nt++) {
                int c = wn + nt * 8 + g;
                bf[nt][0] = __float_as_uint(Bs[cur][k0 + t][c]);
                bf[nt][1] = __float_as_uint(Bs[cur][k0 + t + 4][c]);
            }
            #pragma unroll
            for (int mt = 0; mt < 2; mt++)
                #pragma unroll
                for (int nt = 0; nt < 8; nt++)
                    mma8(acc[mt][nt], a[mt], bf[nt]);
        }

        if (kt + 1 < ntile) {
            As[nxt][am][ak+0] = f2tf(pa0.x); As[nxt][am][ak+1] = f2tf(pa0.y);
            As[nxt][am][ak+2] = f2tf(pa0.z); As[nxt][am][ak+3] = f2tf(pa0.w);
            As[nxt][am+64][ak+0] = f2tf(pa1.x); As[nxt][am+64][ak+1] = f2tf(pa1.y);
            As[nxt][am+64][ak+2] = f2tf(pa1.z); As[nxt][am+64][ak+3] = f2tf(pa1.w);
            Bs[nxt][bk][bn4+0] = f2tf(pb0.x); Bs[nxt][bk][bn4+1] = f2tf(pb0.y);
            Bs[nxt][bk][bn4+2] = f2tf(pb0.z); Bs[nxt][bk][bn4+3] = f2tf(pb0.w);
            Bs[nxt][bk+8][bn4+0] = f2tf(pb1.x); Bs[nxt][bk+8][bn4+1] = f2tf(pb1.y);
            Bs[nxt][bk+8][bn4+2] = f2tf(pb1.z); Bs[nxt][bk+8][bn4+3] = f2tf(pb1.w);
        }
        __syncthreads();
    }

    #pragma unroll
    for (int mt = 0; mt < 2; mt++)
        #pragma unroll
        for (int nt = 0; nt < 8; nt++) {
            int r = bm + wm + mt * 16 + g;
            int c = bn + wn + nt * 8 + 2 * t;
            *(float2*)&C[(size_t)r * N + c] = make_float2(acc[mt][nt][0], acc[mt][nt][1]);
            *(float2*)&C[(size_t)(r + 8) * N + c] = make_float2(acc[mt][nt][2], acc[mt][nt][3]);
        }
}

__global__ __launch_bounds__(256, 2) void proj4_kernel(const float* __restrict__ x,
    const float* __restrict__ WQ, const float* __restrict__ WK,
    const float* __restrict__ WV, const float* __restrict__ WG,
    float* Qo, float* Ko, float* Vo, float* Go)
{
    const float* Bp; float* Cp;
    switch (blockIdx.z) {
        case 0:  Bp = WQ; Cp = Qo; break;
        case 1:  Bp = WK; Cp = Ko; break;
        case 2:  Bp = WV; Cp = Vo; break;
        default: Bp = WG; Cp = Go; break;
    }
    gemm_body(x, Bp, Cp, MT, DD, DD);
}

__global__ __launch_bounds__(256, 2) void gemm_kernel(const float* __restrict__ A,
                                                      const float* __restrict__ B,
                                                      float* __restrict__ C)
{
    gemm_body(A, B, C, MT, DD, DD);
}

// ============================================================
// Chunkwise retention.
// QSTR=68: A-operand arrays ([row][k]); KSTR=76 works as BOTH
// A-operand ((12g+t)%32 distinct) and B-operand ((12t+g)%32 distinct).
// ============================================================
#define QSTR 68
#define KSTR 76

// K1: per (c,h,b): B_c[d][e] = sum_j K[j][d] * (gamma^(C-j) V[j][e])
__global__ __launch_bounds__(256) void chunk_outer(const float* __restrict__ K,
                                                   const float* __restrict__ V,
                                                   float* __restrict__ Bout)
{
    __shared__ float Ks[64 * KSTR];   // [d][j]
    __shared__ float Vd[64 * KSTR];   // [j][e] decayed

    int c = blockIdx.x, h = blockIdx.y, b = blockIdx.z;
    int tid = threadIdx.x;
    int w = tid >> 5, lane = tid & 31;
    int g = lane >> 2, t = lane & 3;
    int wi = (w >> 2) * 32, wj = (w & 3) * 16;

    float log2g = log2f(1.f - exp2f(-5.f - (float)h));

    int lr = tid >> 2, lc = (tid & 3) * 4;
    const float* Kb = K + ((size_t)b * TT + (size_t)c * CS) * DD + h * DH;
    const float* Vb = V + ((size_t)b * TT + (size_t)c * CS) * DD + h * DH;
    float dec = exp2f(log2g * (float)(CS - lr));   // gamma^(C-j), j=lr

    #pragma unroll
    for (int p = 0; p < 4; p++) {
        int c0 = lc + p * 16;
        float4 kv = *(const float4*)&Kb[(size_t)lr * DD + c0];
        Ks[(c0 + 0) * KSTR + lr] = f2tf(kv.x);
        Ks[(c0 + 1) * KSTR + lr] = f2tf(kv.y);
        Ks[(c0 + 2) * KSTR + lr] = f2tf(kv.z);
        Ks[(c0 + 3) * KSTR + lr] = f2tf(kv.w);
        float4 vv = *(const float4*)&Vb[(size_t)lr * DD + c0];
        float4 vd = make_float4(f2tf(dec * vv.x), f2tf(dec * vv.y),
                                f2tf(dec * vv.z), f2tf(dec * vv.w));
        *(float4*)&Vd[lr * KSTR + c0] = vd;
    }
    __syncthreads();

    float bacc[2][2][4];
    #pragma unroll
    for (int i = 0; i < 2; i++)
        #pragma unroll
        for (int j = 0; j < 2; j++)
            #pragma unroll
            for (int q = 0; q < 4; q++) bacc[i][j][q] = 0.f;

    #pragma unroll
    for (int j8 = 0; j8 < 8; j8++) {
        int k0 = j8 * 8;
        unsigned a[2][4], bf[2][2];
        #pragma unroll
        for (int mt = 0; mt < 2; mt++) {
            int r = wi + mt * 16;
            a[mt][0] = __float_as_uint(Ks[(r + g) * KSTR + k0 + t]);
            a[mt][1] = __float_as_uint(Ks[(r + 8 + g) * KSTR + k0 + t]);
            a[mt][2] = __float_as_uint(Ks[(r + g) * KSTR + k0 + t + 4]);
            a[mt][3] = __float_as_uint(Ks[(r + 8 + g) * KSTR + k0 + t + 4]);
        }
        #pragma unroll
        for (int nt = 0; nt < 2; nt++) {
            int cc = wj + nt * 8 + g;
            bf[nt][0] = __float_as_uint(Vd[(k0 + t) * KSTR + cc]);
            bf[nt][1] = __float_as_uint(Vd[(k0 + t + 4) * KSTR + cc]);
        }
        #pragma unroll
        for (int mt = 0; mt < 2; mt++)
            #pragma unroll
            for (int nt = 0; nt < 2; nt++)
                mma8(bacc[mt][nt], a[mt], bf[nt]);
    }

    size_t base = (((size_t)(b * HH + h)) * NC + c) * (DH * DH);
    #pragma unroll
    for (int mt = 0; mt < 2; mt++)
        #pragma unroll
        for (int nt = 0; nt < 2; nt++) {
            int r = wi + mt * 16 + g;
            int cc = wj + nt * 8 + 2 * t;
            *(float2*)&Bout[base + r * DH + cc] = make_float2(bacc[mt][nt][0], bacc[mt][nt][1]);
            *(float2*)&Bout[base + (r + 8) * DH + cc] = make_float2(bacc[mt][nt][2], bacc[mt][nt][3]);
        }
}

// K2a: elementwise scan over chunks: S_c = sum_{c'<c} gamma^{(c-1-c')C} B_{c'}
__global__ __launch_bounds__(256) void scan_state(const float* __restrict__ Bm,
                                                  float* __restrict__ Sm)
{
    int bh = blockIdx.x;          // b*8+h
    int part = blockIdx.y;        // 0..7, 512 elements each
    int h = bh & 7;
    float log2g = log2f(1.f - exp2f(-5.f - (float)h));
    float gc = exp2f(64.f * log2g);

    size_t base = (size_t)bh * NC * (DH * DH) + part * 512 + threadIdx.x;
    float s0 = 0.f, s1 = 0.f;
    for (int c = 0; c < NC; c++) {
        size_t o = base + (size_t)c * (DH * DH);
        Sm[o] = s0;        s0 = gc * s0 + Bm[o];
        Sm[o + 256] = s1;  s1 = gc * s1 + Bm[o + 256];
    }
}

// K2b: per (c,h,b): intra quadratic + inter via state + GroupNorm + SiLU gate.
#define RET_SMEM ((2*64*QSTR + 3*64*KSTR) * 4)

__global__ __launch_bounds__(256) void retention_chunk(
    const float* __restrict__ Q, const float* __restrict__ K,
    const float* __restrict__ V, const float* __restrict__ Sm,
    const float* __restrict__ G, const float* __restrict__ gnw,
    const float* __restrict__ gnb, float* __restrict__ Y)
{
    extern __shared__ float sm[];
    float* Qs = sm;                   // [i][d] 68, Q/8
    float* Ss = Qs + 64 * QSTR;       // [i][j] 68 (later reused as Os)
    float* Ks = Ss + 64 * QSTR;       // [d][j] 76
    float* Vd = Ks + 64 * KSTR;       // [j][e] 76, gamma^(C-j) V
    float* Ts = Vd + 64 * KSTR;       // [d][e] 76, state

    int c = blockIdx.x, h = blockIdx.y, b = blockIdx.z;
    int tid = threadIdx.x;
    int w = tid >> 5, lane = tid & 31;
    int g = lane >> 2, t = lane & 3;
    int wi = (w >> 2) * 32, wj = (w & 3) * 16;

    float log2g = log2f(1.f - exp2f(-5.f - (float)h));

    int lr = tid >> 2, lc = (tid & 3) * 4;
    const float* Qb = Q + ((size_t)b * TT + (size_t)c * CS) * DD + h * DH;
    const float* Kb = K + ((size_t)b * TT + (size_t)c * CS) * DD + h * DH;
    const float* Vb = V + ((size_t)b * TT + (size_t)c * CS) * DD + h * DH;
    const float* Tb = Sm + (((size_t)(b * HH + h)) * NC + c) * (DH * DH);
    float dec = exp2f(log2g * (float)(CS - lr));

    #pragma unroll
    for (int p = 0; p < 4; p++) {
        int c0 = lc + p * 16;
        float4 qv = *(const float4*)&Qb[(size_t)lr * DD + c0];
        Qs[lr * QSTR + c0 + 0] = f2tf(0.125f * qv.x);
        Qs[lr * QSTR + c0 + 1] = f2tf(0.125f * qv.y);
        Qs[lr * QSTR + c0 + 2] = f2tf(0.125f * qv.z);
        Qs[lr * QSTR + c0 + 3] = f2tf(0.125f * qv.w);
        float4 kv = *(const float4*)&Kb[(size_t)lr * DD + c0];
        Ks[(c0 + 0) * KSTR + lr] = f2tf(kv.x);
        Ks[(c0 + 1) * KSTR + lr] = f2tf(kv.y);
        Ks[(c0 + 2) * KSTR + lr] = f2tf(kv.z);
        Ks[(c0 + 3) * KSTR + lr] = f2tf(kv.w);
        float4 vv = *(const float4*)&Vb[(size_t)lr * DD + c0];
        float4 vd = make_float4(f2tf(dec * vv.x), f2tf(dec * vv.y),
                                f2tf(dec * vv.z), f2tf(dec * vv.w));
        *(float4*)&Vd[lr * KSTR + c0] = vd;
        float4 tv = *(const float4*)&Tb[lr * DH + c0];
        float4 td = make_float4(f2tf(tv.x), f2tf(tv.y), f2tf(tv.z), f2tf(tv.w));
        *(float4*)&Ts[lr * KSTR + c0] = td;
    }
    __syncthreads();

    // --- S = Qs @ Ks (intra scores) and iacc = Qs @ Ts (inter) ---
    float sacc[2][2][4], iacc[2][2][4];
    #pragma unroll
    for (int i = 0; i < 2; i++)
        #pragma unroll
        for (int j = 0; j < 2; j++)
            #pragma unroll
            for (int q = 0; q < 4; q++) { sacc[i][j][q] = 0.f; iacc[i][j][q] = 0.f; }

    #pragma unroll
    for (int d8 = 0; d8 < 8; d8++) {
        int k0 = d8 * 8;
        unsigned a[2][4], bk_[2][2], bt[2][2];
        #pragma unroll
        for (int mt = 0; mt < 2; mt++) {
            int r = wi + mt * 16;
            a[mt][0] = __float_as_uint(Qs[(r + g) * QSTR + k0 + t]);
            a[mt][1] = __float_as_uint(Qs[(r + 8 + g) * QSTR + k0 + t]);
            a[mt][2] = __float_as_uint(Qs[(r + g) * QSTR + k0 + t + 4]);
            a[mt][3] = __float_as_uint(Qs[(r + 8 + g) * QSTR + k0 + t + 4]);
        }
        #pragma unroll
        for (int nt = 0; nt < 2; nt++) {
            int cc = wj + nt * 8 + g;
            bk_[nt][0] = __float_as_uint(Ks[(k0 + t) * KSTR + cc]);
            bk_[nt][1] = __float_as_uint(Ks[(k0 + t + 4) * KSTR + cc]);
            bt[nt][0] = __float_as_uint(Ts[(k0 + t) * KSTR + cc]);
            bt[nt][1] = __float_as_uint(Ts[(k0 + t + 4) * KSTR + cc]);
        }
        #pragma unroll
        for (int mt = 0; mt < 2; mt++)
            #pragma unroll
            for (int nt = 0; nt < 2; nt++) {
                mma8(sacc[mt][nt], a[mt], bk_[nt]);
                mma8(iacc[mt][nt], a[mt], bt[nt]);
            }
    }

    // decay-mask S with gamma^(i-64) (pairs with gamma^(64-j) folded into Vd)
    #pragma unroll
    for (int mt = 0; mt < 2; mt++) {
        #pragma unroll
        for (int nt = 0; nt < 2; nt++) {
            int r0 = wi + mt * 16 + g;
            int c0 = wj + nt * 8 + 2 * t;
            #pragma unroll
            for (int e = 0; e < 4; e++) {
                int r = r0 + (e >> 1) * 8;
                int cc = c0 + (e & 1);
                float wgt = (r >= cc) ? exp2f(log2g * (float)(r - 64)) : 0.f;
                Ss[r * QSTR + cc] = f2tf(sacc[mt][nt][e] * wgt);
            }
        }
    }
    __syncthreads();

    // --- O_intra = Ss @ Vd ---
    float oacc[2][2][4];
    #pragma unroll
    for (int i = 0; i < 2; i++)
        #pragma unroll
        for (int j = 0; j < 2; j++)
            #pragma unroll
            for (int q = 0; q < 4; q++) oacc[i][j][q] = 0.f;

    #pragma unroll
    for (int m8 = 0; m8 < 8; m8++) {
        int k0 = m8 * 8;
        unsigned a[2][4], bf[2][2];
        #pragma unroll
        for (int mt = 0; mt < 2; mt++) {
            int r = wi + mt * 16;
            a[mt][0] = __float_as_uint(Ss[(r + g) * QSTR + k0 + t]);
            a[mt][1] = __float_as_uint(Ss[(r + 8 + g) * QSTR + k0 + t]);
            a[mt][2] = __float_as_uint(Ss[(r + g) * QSTR + k0 + t + 4]);
            a[mt][3] = __float_as_uint(Ss[(r + 8 + g) * QSTR + k0 + t + 4]);
        }
        #pragma unroll
        for (int nt = 0; nt < 2; nt++) {
            int cc = wj + nt * 8 + g;
            bf[nt][0] = __float_as_uint(Vd[(k0 + t) * KSTR + cc]);
            bf[nt][1] = __float_as_uint(Vd[(k0 + t + 4) * KSTR + cc]);
        }
        #pragma unroll
        for (int mt = 0; mt < 2; mt++)
            #pragma unroll
            for (int nt = 0; nt < 2; nt++)
                mma8(oacc[mt][nt], a[mt], bf[nt]);
    }
    __syncthreads();   // all reads of Ss done; safe to reuse as Os

    // combine intra + gamma^i * inter, stage to Os(=Ss)
    #pragma unroll
    for (int mt = 0; mt < 2; mt++) {
        #pragma unroll
        for (int nt = 0; nt < 2; nt++) {
            int r0 = wi + mt * 16 + g;
            int c0 = wj + nt * 8 + 2 * t;
            float scA = exp2f(log2g * (float)r0);
            float scB = exp2f(log2g * (float)(r0 + 8));
            Ss[r0 * QSTR + c0]           = oacc[mt][nt][0] + scA * iacc[mt][nt][0];
            Ss[r0 * QSTR + c0 + 1]       = oacc[mt][nt][1] + scA * iacc[mt][nt][1];
            Ss[(r0 + 8) * QSTR + c0]     = oacc[mt][nt][2] + scB * iacc[mt][nt][2];
            Ss[(r0 + 8) * QSTR + c0 + 1] = oacc[mt][nt][3] + scB * iacc[mt][nt][3];
        }
    }
    __syncthreads();

    // --- GroupNorm over this head's 64 channels + SiLU gate ---
    int tok = tid >> 2, sub = tid & 3;
    float vals[16];
    float s = 0.f, sq = 0.f;
    #pragma unroll
    for (int u = 0; u < 16; u++) {
        float v = Ss[tok * QSTR + sub * 16 + u];
        vals[u] = v; s += v; sq += v * v;
    }
    s  += __shfl_xor_sync(0xffffffffu, s, 1);
    s  += __shfl_xor_sync(0xffffffffu, s, 2);
    sq += __shfl_xor_sync(0xffffffffu, sq, 1);
    sq += __shfl_xor_sync(0xffffffffu, sq, 2);
    float mean = s * (1.f / 64.f);
    float inv = rsqrtf(sq * (1.f / 64.f) - mean * mean + 1e-5f);

    size_t row = (size_t)b * TT + (size_t)c * CS + tok;
    int wcol = h * DH + sub * 16;
    const float* gp = G + row * DD + wcol;
    float* yp = Y + row * DD + wcol;
    #pragma unroll
    for (int u4 = 0; u4 < 4; u4++) {
        float4 wv = *(const float4*)&gnw[wcol + u4 * 4];
        float4 bv = *(const float4*)&gnb[wcol + u4 * 4];
        float4 gv = *(const float4*)&gp[u4 * 4];
        float4 yv;
        float z;
        z = gv.x + (vals[u4*4+0] - mean) * inv * wv.x + bv.x; yv.x = z / (1.f + expf(-z));
        z = gv.y + (vals[u4*4+1] - mean) * inv * wv.y + bv.y; yv.y = z / (1.f + expf(-z));
        z = gv.z + (vals[u4*4+2] - mean) * inv * wv.z + bv.z; yv.z = z / (1.f + expf(-z));
        z = gv.w + (vals[u4*4+3] - mean) * inv * wv.w + bv.w; yv.w = z / (1.f + expf(-z));
        *(float4*)&yp[u4 * 4] = yv;
    }
}

// ============================================================
extern "C" void kernel_launch(void* const* d_in, const int* in_sizes, int n_in,
                              void* d_out, int out_size) {
    const float* x   = (const float*)d_in[0];
    const float* WQ  = (const float*)d_in[1];
    const float* WK  = (const float*)d_in[2];
    const float* WV  = (const float*)d_in[3];
    const float* WG  = (const float*)d_in[4];
    const float* WO  = (const float*)d_in[5];
    const float* gnw = (const float*)d_in[6];
    const float* gnb = (const float*)d_in[7];
    float* out = (float*)d_out;

    float *Qp, *Kp, *Vp, *Gp, *Yp, *Bp, *Sp;
    cudaGetSymbolAddress((void**)&Qp, g_Q);
    cudaGetSymbolAddress((void**)&Kp, g_K);
    cudaGetSymbolAddress((void**)&Vp, g_V);
    cudaGetSymbolAddress((void**)&Gp, g_G);
    cudaGetSymbolAddress((void**)&Yp, g_Y);
    cudaGetSymbolAddress((void**)&Bp, g_B);
    cudaGetSymbolAddress((void**)&Sp, g_S);

    cudaFuncSetAttribute(retention_chunk,
                         cudaFuncAttributeMaxDynamicSharedMemorySize, RET_SMEM);

    proj4_kernel<<<dim3(DD / 128, MT / 128, 4), 256>>>(x, WQ, WK, WV, WG,
                                                       Qp, Kp, Vp, Gp);

    chunk_outer<<<dim3(NC, HH, BB), 256>>>(Kp, Vp, Bp);

    scan_state<<<dim3(BB * HH, 8), 256>>>(Bp, Sp);

    retention_chunk<<<dim3(NC, HH, BB), 256, RET_SMEM>>>(Qp, Kp, Vp, Sp,
                                                         Gp, gnw, gnb, Yp);

    gemm_kernel<<<dim3(DD / 128, MT / 128, 1), 256>>>(Yp, WO, out);
}

// round 5
// speedup vs baseline: 5.7590x; 1.0176x over previous
#include <cuda_runtime.h>
#include <math.h>

#define BB 2
#define TT 2048
#define DD 512
#define HH 8
#define DH 64
#define MT (BB*TT)   // 4096
#define NC 32        // chunks per sequence
#define CS 64        // chunk size

// ---- scratch (static device globals; no allocation) ----
__device__ float g_Q[MT*DD];
__device__ float g_K[MT*DD];
__device__ float g_V[MT*DD];
__device__ float g_G[MT*DD];
__device__ float g_Y[MT*DD];
__device__ float g_B[BB*HH*NC*DH*DH];
__device__ float g_S[BB*HH*NC*DH*DH];

// ---- helpers ----
__device__ __forceinline__ float f2tf(float x) {
    unsigned u;
    asm("cvt.rna.tf32.f32 %0, %1;" : "=r"(u) : "f"(x));
    return __uint_as_float(u);
}
__device__ __forceinline__ unsigned f2tfu(float x) {
    unsigned u;
    asm("cvt.rna.tf32.f32 %0, %1;" : "=r"(u) : "f"(x));
    return u;
}
__device__ __forceinline__ void mma8(float* c, const unsigned* a, const unsigned* b) {
    asm volatile("mma.sync.aligned.m16n8k8.row.col.f32.tf32.tf32.f32 "
        "{%0,%1,%2,%3}, {%4,%5,%6,%7}, {%8,%9}, {%0,%1,%2,%3};\n"
        : "+f"(c[0]), "+f"(c[1]), "+f"(c[2]), "+f"(c[3])
        : "r"(a[0]), "r"(a[1]), "r"(a[2]), "r"(a[3]), "r"(b[0]), "r"(b[1]));
}
__device__ __forceinline__ void cp16(float* smem, const float* g) {
    unsigned s = (unsigned)__cvta_generic_to_shared(smem);
    asm volatile("cp.async.cg.shared.global [%0], [%1], 16;\n" :: "r"(s), "l"(g));
}
#define CP_COMMIT() asm volatile("cp.async.commit_group;\n" ::: "memory")
#define CP_WAIT1()  asm volatile("cp.async.wait_group 1;\n" ::: "memory")

// ============================================================
// tf32 GEMM: C[M,N] = alpha * A[M,K] @ B[K,N]
// 128x128 tile, BK=16, 256 threads, warp 32x64,
// 3-stage cp.async pipeline, tf32 cvt at fragment load.
// ============================================================
#define GAS (128*20)
#define GBS (16*136)
#define GEMM_SMEM ((3*GAS + 3*GBS)*4)   // 56832 bytes

__device__ __forceinline__ void gemm_body(const float* __restrict__ A,
                                          const float* __restrict__ B,
                                          float* __restrict__ C,
                                          int M, int N, int K, float alpha)
{
    extern __shared__ float sm[];
    float* As = sm;            // [3][128][20]
    float* Bs = sm + 3*GAS;    // [3][16][136]

    int tid = threadIdx.x;
    int w = tid >> 5, lane = tid & 31;
    int g = lane >> 2, t = lane & 3;
    int wm = (w >> 1) * 32;
    int wn = (w & 1) * 64;
    int bm = blockIdx.y * 128, bn = blockIdx.x * 128;

    int am = tid >> 2, ak = (tid & 3) * 4;
    int bk = tid >> 5, bn4 = (tid & 31) * 4;

    const float* Ag0 = A + (size_t)(bm + am) * K + ak;
    const float* Ag1 = Ag0 + (size_t)64 * K;
    const float* Bg0 = B + (size_t)bk * N + bn + bn4;
    const float* Bg1 = Bg0 + (size_t)8 * N;

    float acc[2][8][4];
    #pragma unroll
    for (int i = 0; i < 2; i++)
        #pragma unroll
        for (int j = 0; j < 8; j++)
            #pragma unroll
            for (int q = 0; q < 4; q++) acc[i][j][q] = 0.f;

    int ntile = K >> 4;

    // prologue: stages 0,1
    #pragma unroll
    for (int p = 0; p < 2; p++) {
        cp16(&As[p*GAS + am*20 + ak],        Ag0 + p*16);
        cp16(&As[p*GAS + (am+64)*20 + ak],   Ag1 + p*16);
        cp16(&Bs[p*GBS + bk*136 + bn4],      Bg0 + (size_t)(p*16) * N);
        cp16(&Bs[p*GBS + (bk+8)*136 + bn4],  Bg1 + (size_t)(p*16) * N);
        CP_COMMIT();
    }

    for (int kt = 0; kt < ntile; kt++) {
        int cur = kt % 3;
        CP_WAIT1();
        __syncthreads();

        if (kt + 2 < ntile) {
            int s = (kt + 2) % 3;
            int off = (kt + 2) * 16;
            cp16(&As[s*GAS + am*20 + ak],        Ag0 + off);
            cp16(&As[s*GAS + (am+64)*20 + ak],   Ag1 + off);
            cp16(&Bs[s*GBS + bk*136 + bn4],      Bg0 + (size_t)off * N);
            cp16(&Bs[s*GBS + (bk+8)*136 + bn4],  Bg1 + (size_t)off * N);
        }
        CP_COMMIT();

        const float* Ac = As + cur*GAS;
        const float* Bc = Bs + cur*GBS;
        #pragma unroll
        for (int ks = 0; ks < 2; ks++) {
            int k0 = ks * 8;
            unsigned a[2][4], bf[8][2];
            #pragma unroll
            for (int mt = 0; mt < 2; mt++) {
                int r = wm + mt * 16;
                a[mt][0] = f2tfu(Ac[(r + g)*20 + k0 + t]);
                a[mt][1] = f2tfu(Ac[(r + 8 + g)*20 + k0 + t]);
                a[mt][2] = f2tfu(Ac[(r + g)*20 + k0 + t + 4]);
                a[mt][3] = f2tfu(Ac[(r + 8 + g)*20 + k0 + t + 4]);
            }
            #pragma unroll
            for (int nt = 0; nt < 8; nt++) {
                int c = wn + nt * 8 + g;
                bf[nt][0] = f2tfu(Bc[(k0 + t)*136 + c]);
                bf[nt][1] = f2tfu(Bc[(k0 + t + 4)*136 + c]);
            }
            #pragma unroll
            for (int mt = 0; mt < 2; mt++)
                #pragma unroll
                for (int nt = 0; nt < 8; nt++)
                    mma8(acc[mt][nt], a[mt], bf[nt]);
        }
    }

    #pragma unroll
    for (int mt = 0; mt < 2; mt++)
        #pragma unroll
        for (int nt = 0; nt < 8; nt++) {
            int r = bm + wm + mt * 16 + g;
            int c = bn + wn + nt * 8 + 2 * t;
            *(float2*)&C[(size_t)r * N + c] =
                make_float2(alpha * acc[mt][nt][0], alpha * acc[mt][nt][1]);
            *(float2*)&C[(size_t)(r + 8) * N + c] =
                make_float2(alpha * acc[mt][nt][2], alpha * acc[mt][nt][3]);
        }
}

__global__ __launch_bounds__(256, 2) void proj4_kernel(const float* __restrict__ x,
    const float* __restrict__ WQ, const float* __restrict__ WK,
    const float* __restrict__ WV, const float* __restrict__ WG,
    float* Qo, float* Ko, float* Vo, float* Go)
{
    const float* Bp; float* Cp; float alpha = 1.f;
    switch (blockIdx.z) {
        case 0:  Bp = WQ; Cp = Qo; alpha = 0.125f; break;  // fold 1/sqrt(dh)
        case 1:  Bp = WK; Cp = Ko; break;
        case 2:  Bp = WV; Cp = Vo; break;
        default: Bp = WG; Cp = Go; break;
    }
    gemm_body(x, Bp, Cp, MT, DD, DD, alpha);
}

__global__ __launch_bounds__(256, 2) void gemm_kernel(const float* __restrict__ A,
                                                      const float* __restrict__ B,
                                                      float* __restrict__ C)
{
    gemm_body(A, B, C, MT, DD, DD, 1.f);
}

// ============================================================
// Chunkwise retention (tf32 mma).
// ============================================================
#define QSTR 68
#define KSTR 76

// K1: B_c[d][e] = sum_j K[j][d] * (gamma^(C-j) V[j][e])
__global__ __launch_bounds__(256) void chunk_outer(const float* __restrict__ K,
                                                   const float* __restrict__ V,
                                                   float* __restrict__ Bout)
{
    __shared__ float Ks[64 * KSTR];
    __shared__ float Vd[64 * KSTR];

    int c = blockIdx.x, h = blockIdx.y, b = blockIdx.z;
    int tid = threadIdx.x;
    int w = tid >> 5, lane = tid & 31;
    int g = lane >> 2, t = lane & 3;
    int wi = (w >> 2) * 32, wj = (w & 3) * 16;

    float log2g = log2f(1.f - exp2f(-5.f - (float)h));

    int lr = tid >> 2, lc = (tid & 3) * 4;
    const float* Kb = K + ((size_t)b * TT + (size_t)c * CS) * DD + h * DH;
    const float* Vb = V + ((size_t)b * TT + (size_t)c * CS) * DD + h * DH;
    float dec = exp2f(log2g * (float)(CS - lr));

    #pragma unroll
    for (int p = 0; p < 4; p++) {
        int c0 = lc + p * 16;
        float4 kv = *(const float4*)&Kb[(size_t)lr * DD + c0];
        Ks[(c0 + 0) * KSTR + lr] = f2tf(kv.x);
        Ks[(c0 + 1) * KSTR + lr] = f2tf(kv.y);
        Ks[(c0 + 2) * KSTR + lr] = f2tf(kv.z);
        Ks[(c0 + 3) * KSTR + lr] = f2tf(kv.w);
        float4 vv = *(const float4*)&Vb[(size_t)lr * DD + c0];
        float4 vd = make_float4(f2tf(dec * vv.x), f2tf(dec * vv.y),
                                f2tf(dec * vv.z), f2tf(dec * vv.w));
        *(float4*)&Vd[lr * KSTR + c0] = vd;
    }
    __syncthreads();

    float bacc[2][2][4];
    #pragma unroll
    for (int i = 0; i < 2; i++)
        #pragma unroll
        for (int j = 0; j < 2; j++)
            #pragma unroll
            for (int q = 0; q < 4; q++) bacc[i][j][q] = 0.f;

    #pragma unroll
    for (int j8 = 0; j8 < 8; j8++) {
        int k0 = j8 * 8;
        unsigned a[2][4], bf[2][2];
        #pragma unroll
        for (int mt = 0; mt < 2; mt++) {
            int r = wi + mt * 16;
            a[mt][0] = __float_as_uint(Ks[(r + g) * KSTR + k0 + t]);
            a[mt][1] = __float_as_uint(Ks[(r + 8 + g) * KSTR + k0 + t]);
            a[mt][2] = __float_as_uint(Ks[(r + g) * KSTR + k0 + t + 4]);
            a[mt][3] = __float_as_uint(Ks[(r + 8 + g) * KSTR + k0 + t + 4]);
        }
        #pragma unroll
        for (int nt = 0; nt < 2; nt++) {
            int cc = wj + nt * 8 + g;
            bf[nt][0] = __float_as_uint(Vd[(k0 + t) * KSTR + cc]);
            bf[nt][1] = __float_as_uint(Vd[(k0 + t + 4) * KSTR + cc]);
        }
        #pragma unroll
        for (int mt = 0; mt < 2; mt++)
            #pragma unroll
            for (int nt = 0; nt < 2; nt++)
                mma8(bacc[mt][nt], a[mt], bf[nt]);
    }

    size_t base = (((size_t)(b * HH + h)) * NC + c) * (DH * DH);
    #pragma unroll
    for (int mt = 0; mt < 2; mt++)
        #pragma unroll
        for (int nt = 0; nt < 2; nt++) {
            int r = wi + mt * 16 + g;
            int cc = wj + nt * 8 + 2 * t;
            *(float2*)&Bout[base + r * DH + cc] = make_float2(bacc[mt][nt][0], bacc[mt][nt][1]);
            *(float2*)&Bout[base + (r + 8) * DH + cc] = make_float2(bacc[mt][nt][2], bacc[mt][nt][3]);
        }
}

// K2a: scan over chunks
__global__ __launch_bounds__(256) void scan_state(const float* __restrict__ Bm,
                                                  float* __restrict__ Sm)
{
    int bh = blockIdx.x;
    int part = blockIdx.y;
    int h = bh & 7;
    float log2g = log2f(1.f - exp2f(-5.f - (float)h));
    float gc = exp2f(64.f * log2g);

    size_t base = (size_t)bh * NC * (DH * DH) + part * 512 + threadIdx.x;
    float s0 = 0.f, s1 = 0.f;
    for (int c = 0; c < NC; c++) {
        size_t o = base + (size_t)c * (DH * DH);
        Sm[o] = s0;        s0 = gc * s0 + Bm[o];
        Sm[o + 256] = s1;  s1 = gc * s1 + Bm[o + 256];
    }
}

// K2b: intra + inter + GroupNorm + SiLU gate (Q pre-scaled by 1/8)
#define RET_SMEM ((2*64*QSTR + 3*64*KSTR) * 4)

__global__ __launch_bounds__(256) void retention_chunk(
    const float* __restrict__ Q, const float* __restrict__ K,
    const float* __restrict__ V, const float* __restrict__ Sm,
    const float* __restrict__ G, const float* __restrict__ gnw,
    const float* __restrict__ gnb, float* __restrict__ Y)
{
    extern __shared__ float sm[];
    float* Qs = sm;
    float* Ss = Qs + 64 * QSTR;
    float* Ks = Ss + 64 * QSTR;
    float* Vd = Ks + 64 * KSTR;
    float* Ts = Vd + 64 * KSTR;

    int c = blockIdx.x, h = blockIdx.y, b = blockIdx.z;
    int tid = threadIdx.x;
    int w = tid >> 5, lane = tid & 31;
    int g = lane >> 2, t = lane & 3;
    int wi = (w >> 2) * 32, wj = (w & 3) * 16;

    float log2g = log2f(1.f - exp2f(-5.f - (float)h));

    int lr = tid >> 2, lc = (tid & 3) * 4;
    const float* Qb = Q + ((size_t)b * TT + (size_t)c * CS) * DD + h * DH;
    const float* Kb = K + ((size_t)b * TT + (size_t)c * CS) * DD + h * DH;
    const float* Vb = V + ((size_t)b * TT + (size_t)c * CS) * DD + h * DH;
    const float* Tb = Sm + (((size_t)(b * HH + h)) * NC + c) * (DH * DH);
    float dec = exp2f(log2g * (float)(CS - lr));

    #pragma unroll
    for (int p = 0; p < 4; p++) {
        int c0 = lc + p * 16;
        float4 qv = *(const float4*)&Qb[(size_t)lr * DD + c0];
        Qs[lr * QSTR + c0 + 0] = f2tf(qv.x);
        Qs[lr * QSTR + c0 + 1] = f2tf(qv.y);
        Qs[lr * QSTR + c0 + 2] = f2tf(qv.z);
        Qs[lr * QSTR + c0 + 3] = f2tf(qv.w);
        float4 kv = *(const float4*)&Kb[(size_t)lr * DD + c0];
        Ks[(c0 + 0) * KSTR + lr] = f2tf(kv.x);
        Ks[(c0 + 1) * KSTR + lr] = f2tf(kv.y);
        Ks[(c0 + 2) * KSTR + lr] = f2tf(kv.z);
        Ks[(c0 + 3) * KSTR + lr] = f2tf(kv.w);
        float4 vv = *(const float4*)&Vb[(size_t)lr * DD + c0];
        float4 vd = make_float4(f2tf(dec * vv.x), f2tf(dec * vv.y),
                                f2tf(dec * vv.z), f2tf(dec * vv.w));
        *(float4*)&Vd[lr * KSTR + c0] = vd;
        float4 tv = *(const float4*)&Tb[lr * DH + c0];
        float4 td = make_float4(f2tf(tv.x), f2tf(tv.y), f2tf(tv.z), f2tf(tv.w));
        *(float4*)&Ts[lr * KSTR + c0] = td;
    }
    __syncthreads();

    float sacc[2][2][4], iacc[2][2][4];
    #pragma unroll
    for (int i = 0; i < 2; i++)
        #pragma unroll
        for (int j = 0; j < 2; j++)
            #pragma unroll
            for (int q = 0; q < 4; q++) { sacc[i][j][q] = 0.f; iacc[i][j][q] = 0.f; }

    #pragma unroll
    for (int d8 = 0; d8 < 8; d8++) {
        int k0 = d8 * 8;
        unsigned a[2][4], bk_[2][2], bt[2][2];
        #pragma unroll
        for (int mt = 0; mt < 2; mt++) {
            int r = wi + mt * 16;
            a[mt][0] = __float_as_uint(Qs[(r + g) * QSTR + k0 + t]);
            a[mt][1] = __float_as_uint(Qs[(r + 8 + g) * QSTR + k0 + t]);
            a[mt][2] = __float_as_uint(Qs[(r + g) * QSTR + k0 + t + 4]);
            a[mt][3] = __float_as_uint(Qs[(r + 8 + g) * QSTR + k0 + t + 4]);
        }
        #pragma unroll
        for (int nt = 0; nt < 2; nt++) {
            int cc = wj + nt * 8 + g;
            bk_[nt][0] = __float_as_uint(Ks[(k0 + t) * KSTR + cc]);
            bk_[nt][1] = __float_as_uint(Ks[(k0 + t + 4) * KSTR + cc]);
            bt[nt][0] = __float_as_uint(Ts[(k0 + t) * KSTR + cc]);
            bt[nt][1] = __float_as_uint(Ts[(k0 + t + 4) * KSTR + cc]);
        }
        #pragma unroll
        for (int mt = 0; mt < 2; mt++)
            #pragma unroll
            for (int nt = 0; nt < 2; nt++) {
                mma8(sacc[mt][nt], a[mt], bk_[nt]);
                mma8(iacc[mt][nt], a[mt], bt[nt]);
            }
    }

    #pragma unroll
    for (int mt = 0; mt < 2; mt++) {
        #pragma unroll
        for (int nt = 0; nt < 2; nt++) {
            int r0 = wi + mt * 16 + g;
            int c0 = wj + nt * 8 + 2 * t;
            #pragma unroll
            for (int e = 0; e < 4; e++) {
                int r = r0 + (e >> 1) * 8;
                int cc = c0 + (e & 1);
                float wgt = (r >= cc) ? exp2f(log2g * (float)(r - 64)) : 0.f;
                Ss[r * QSTR + cc] = f2tf(sacc[mt][nt][e] * wgt);
            }
        }
    }
    __syncthreads();

    float oacc[2][2][4];
    #pragma unroll
    for (int i = 0; i < 2; i++)
        #pragma unroll
        for (int j = 0; j < 2; j++)
            #pragma unroll
            for (int q = 0; q < 4; q++) oacc[i][j][q] = 0.f;

    #pragma unroll
    for (int m8 = 0; m8 < 8; m8++) {
        int k0 = m8 * 8;
        unsigned a[2][4], bf[2][2];
        #pragma unroll
        for (int mt = 0; mt < 2; mt++) {
            int r = wi + mt * 16;
            a[mt][0] = __float_as_uint(Ss[(r + g) * QSTR + k0 + t]);
            a[mt][1] = __float_as_uint(Ss[(r + 8 + g) * QSTR + k0 + t]);
            a[mt][2] = __float_as_uint(Ss[(r + g) * QSTR + k0 + t + 4]);
            a[mt][3] = __float_as_uint(Ss[(r + 8 + g) * QSTR + k0 + t + 4]);
        }
        #pragma unroll
        for (int nt = 0; nt < 2; nt++) {
            int cc = wj + nt * 8 + g;
            bf[nt][0] = __float_as_uint(Vd[(k0 + t) * KSTR + cc]);
            bf[nt][1] = __float_as_uint(Vd[(k0 + t + 4) * KSTR + cc]);
        }
        #pragma unroll
        for (int mt = 0; mt < 2; mt++)
            #pragma unroll
            for (int nt = 0; nt < 2; nt++)
                mma8(oacc[mt][nt], a[mt], bf[nt]);
    }
    __syncthreads();

    #pragma unroll
    for (int mt = 0; mt < 2; mt++) {
        #pragma unroll
        for (int nt = 0; nt < 2; nt++) {
            int r0 = wi + mt * 16 + g;
            int c0 = wj + nt * 8 + 2 * t;
            float scA = exp2f(log2g * (float)r0);
            float scB = exp2f(log2g * (float)(r0 + 8));
            Ss[r0 * QSTR + c0]           = oacc[mt][nt][0] + scA * iacc[mt][nt][0];
            Ss[r0 * QSTR + c0 + 1]       = oacc[mt][nt][1] + scA * iacc[mt][nt][1];
            Ss[(r0 + 8) * QSTR + c0]     = oacc[mt][nt][2] + scB * iacc[mt][nt][2];
            Ss[(r0 + 8) * QSTR + c0 + 1] = oacc[mt][nt][3] + scB * iacc[mt][nt][3];
        }
    }
    __syncthreads();

    int tok = tid >> 2, sub = tid & 3;
    float vals[16];
    float s = 0.f, sq = 0.f;
    #pragma unroll
    for (int u = 0; u < 16; u++) {
        float v = Ss[tok * QSTR + sub * 16 + u];
        vals[u] = v; s += v; sq += v * v;
    }
    s  += __shfl_xor_sync(0xffffffffu, s, 1);
    s  += __shfl_xor_sync(0xffffffffu, s, 2);
    sq += __shfl_xor_sync(0xffffffffu, sq, 1);
    sq += __shfl_xor_sync(0xffffffffu, sq, 2);
    float mean = s * (1.f / 64.f);
    float inv = rsqrtf(sq * (1.f / 64.f) - mean * mean + 1e-5f);

    size_t row = (size_t)b * TT + (size_t)c * CS + tok;
    int wcol = h * DH + sub * 16;
    const float* gp = G + row * DD + wcol;
    float* yp = Y + row * DD + wcol;
    #pragma unroll
    for (int u4 = 0; u4 < 4; u4++) {
        float4 wv = *(const float4*)&gnw[wcol + u4 * 4];
        float4 bv = *(const float4*)&gnb[wcol + u4 * 4];
        float4 gv = *(const float4*)&gp[u4 * 4];
        float4 yv;
        float z;
        z = gv.x + (vals[u4*4+0] - mean) * inv * wv.x + bv.x; yv.x = z / (1.f + expf(-z));
        z = gv.y + (vals[u4*4+1] - mean) * inv * wv.y + bv.y; yv.y = z / (1.f + expf(-z));
        z = gv.z + (vals[u4*4+2] - mean) * inv * wv.z + bv.z; yv.z = z / (1.f + expf(-z));
        z = gv.w + (vals[u4*4+3] - mean) * inv * wv.w + bv.w; yv.w = z / (1.f + expf(-z));
        *(float4*)&yp[u4 * 4] = yv;
    }
}

// ============================================================
extern "C" void kernel_launch(void* const* d_in, const int* in_sizes, int n_in,
                              void* d_out, int out_size) {
    const float* x   = (const float*)d_in[0];
    const float* WQ  = (const float*)d_in[1];
    const float* WK  = (const float*)d_in[2];
    const float* WV  = (const float*)d_in[3];
    const float* WG  = (const float*)d_in[4];
    const float* WO  = (const float*)d_in[5];
    const float* gnw = (const float*)d_in[6];
    const float* gnb = (const float*)d_in[7];
    float* out = (float*)d_out;

    float *Qp, *Kp, *Vp, *Gp, *Yp, *Bp, *Sp;
    cudaGetSymbolAddress((void**)&Qp, g_Q);
    cudaGetSymbolAddress((void**)&Kp, g_K);
    cudaGetSymbolAddress((void**)&Vp, g_V);
    cudaGetSymbolAddress((void**)&Gp, g_G);
    cudaGetSymbolAddress((void**)&Yp, g_Y);
    cudaGetSymbolAddress((void**)&Bp, g_B);
    cudaGetSymbolAddress((void**)&Sp, g_S);

    cudaFuncSetAttribute(proj4_kernel,
                         cudaFuncAttributeMaxDynamicSharedMemorySize, GEMM_SMEM);
    cudaFuncSetAttribute(gemm_kernel,
                         cudaFuncAttributeMaxDynamicSharedMemorySize, GEMM_SMEM);
    cudaFuncSetAttribute(retention_chunk,
                         cudaFuncAttributeMaxDynamicSharedMemorySize, RET_SMEM);

    proj4_kernel<<<dim3(DD / 128, MT / 128, 4), 256, GEMM_SMEM>>>(
        x, WQ, WK, WV, WG, Qp, Kp, Vp, Gp);

    chunk_outer<<<dim3(NC, HH, BB), 256>>>(Kp, Vp, Bp);

    scan_state<<<dim3(BB * HH, 8), 256>>>(Bp, Sp);

    retention_chunk<<<dim3(NC, HH, BB), 256, RET_SMEM>>>(Qp, Kp, Vp, Sp,
                                                         Gp, gnw, gnb, Yp);

    gemm_kernel<<<dim3(DD / 128, MT / 128, 1), 256, GEMM_SMEM>>>(Yp, WO, out);
}

// round 7
// speedup vs baseline: 6.0265x; 1.0464x over previous
#include <cuda_runtime.h>
#include <math.h>

#define BB 2
#define TT 2048
#define DD 512
#define HH 8
#define DH 64
#define MT (BB*TT)   // 4096
#define NC 32
#define CS 64

// ---- scratch (static device globals; no allocation) ----
__device__ float g_X[MT*DD];          // tf32-converted x
__device__ float g_W5[5*DD*DD];       // tf32-converted weights
__device__ float g_Q[MT*DD];
__device__ float g_K[MT*DD];
__device__ float g_V[MT*DD];
__device__ float g_G[MT*DD];
__device__ float g_Y[MT*DD];
__device__ float g_B[BB*HH*NC*DH*DH];
__device__ float g_S[BB*HH*NC*DH*DH];

// ---- helpers ----
__device__ __forceinline__ float f2tf(float x) {
    unsigned u;
    asm("cvt.rna.tf32.f32 %0, %1;" : "=r"(u) : "f"(x));
    return __uint_as_float(u);
}
__device__ __forceinline__ void mma8(float* c, const unsigned* a, const unsigned* b) {
    asm volatile("mma.sync.aligned.m16n8k8.row.col.f32.tf32.tf32.f32 "
        "{%0,%1,%2,%3}, {%4,%5,%6,%7}, {%8,%9}, {%0,%1,%2,%3};\n"
        : "+f"(c[0]), "+f"(c[1]), "+f"(c[2]), "+f"(c[3])
        : "r"(a[0]), "r"(a[1]), "r"(a[2]), "r"(a[3]), "r"(b[0]), "r"(b[1]));
}
__device__ __forceinline__ void cp16(float* smem, const float* g) {
    unsigned s = (unsigned)__cvta_generic_to_shared(smem);
    asm volatile("cp.async.cg.shared.global [%0], [%1], 16;\n" :: "r"(s), "l"(g));
}
#define CP_COMMIT() asm volatile("cp.async.commit_group;\n" ::: "memory")
#define CP_WAIT1()  asm volatile("cp.async.wait_group 1;\n" ::: "memory")

// ============================================================
// tf32 pre-conversion: x and the five 512x512 weights.
// ============================================================
__global__ __launch_bounds__(256) void conv_tf32(
    const float* __restrict__ x,
    const float* __restrict__ w0, const float* __restrict__ w1,
    const float* __restrict__ w2, const float* __restrict__ w3,
    const float* __restrict__ w4,
    float* __restrict__ xo, float* __restrict__ wo)
{
    int z = blockIdx.z;
    if (z == 0) {
        int i = blockIdx.x * 256 + threadIdx.x;   // 524288 float4
        float4 v = ((const float4*)x)[i];
        ((float4*)xo)[i] = make_float4(f2tf(v.x), f2tf(v.y), f2tf(v.z), f2tf(v.w));
    } else {
        if (blockIdx.x >= 256) return;            // 65536 float4 per weight
        const float* s = (z==1)?w0:(z==2)?w1:(z==3)?w2:(z==4)?w3:w4;
        float* d = wo + (size_t)(z-1) * DD * DD;
        int i = blockIdx.x * 256 + threadIdx.x;
        float4 v = ((const float4*)s)[i];
        ((float4*)d)[i] = make_float4(f2tf(v.x), f2tf(v.y), f2tf(v.z), f2tf(v.w));
    }
}

// ============================================================
// tf32 GEMM: C = alpha * A @ B. A,B already tf32-in-fp32.
// CTA 128x128, 4 warps of 64x64, BK=16, 3-stage cp.async.
// ============================================================
#define GAS (128*20)
#define GBS (16*136)
#define GEMM_SMEM ((3*GAS + 3*GBS)*4)   // 56832 bytes

__device__ __forceinline__ void gemm_body(const float* __restrict__ A,
                                          const float* __restrict__ B,
                                          float* __restrict__ C,
                                          int M, int N, int K, float alpha)
{
    extern __shared__ float sm[];
    float* As = sm;            // [3][128][20]
    float* Bs = sm + 3*GAS;    // [3][16][136]

    int tid = threadIdx.x;               // 0..127
    int w = tid >> 5, lane = tid & 31;
    int g = lane >> 2, t = lane & 3;
    int wm = (w >> 1) * 64;              // 0,64
    int wn = (w & 1) * 64;               // 0,64
    int bm = blockIdx.y * 128, bn = blockIdx.x * 128;

    int ar = tid >> 2, ac = (tid & 3) * 4;     // A: rows ar+32j
    int br = tid >> 5, bc = (tid & 31) * 4;    // B: rows br+4j

    const float* Ag = A + (size_t)(bm + ar) * K + ac;
    const float* Bg = B + (size_t)br * N + bn + bc;

    float acc[4][8][4];
    #pragma unroll
    for (int i = 0; i < 4; i++)
        #pragma unroll
        for (int j = 0; j < 8; j++)
            #pragma unroll
            for (int q = 0; q < 4; q++) acc[i][j][q] = 0.f;

    int ntile = K >> 4;

    // prologue: stages 0,1
    #pragma unroll
    for (int p = 0; p < 2; p++) {
        #pragma unroll
        for (int j = 0; j < 4; j++) {
            cp16(&As[p*GAS + (ar + 32*j)*20 + ac], Ag + (size_t)(32*j) * K + p*16);
            cp16(&Bs[p*GBS + (br + 4*j)*136 + bc], Bg + (size_t)(p*16 + 4*j) * N);
        }
        CP_COMMIT();
    }

    for (int kt = 0; kt < ntile; kt++) {
        int cur = kt % 3;
        CP_WAIT1();
        __syncthreads();

        if (kt + 2 < ntile) {
            int s = (kt + 2) % 3;
            int off = (kt + 2) * 16;
            #pragma unroll
            for (int j = 0; j < 4; j++) {
                cp16(&As[s*GAS + (ar + 32*j)*20 + ac], Ag + (size_t)(32*j) * K + off);
                cp16(&Bs[s*GBS + (br + 4*j)*136 + bc], Bg + (size_t)(off + 4*j) * N);
            }
        }
        CP_COMMIT();

        const float* Ac = As + cur*GAS;
        const float* Bc = Bs + cur*GBS;
        #pragma unroll
        for (int ks = 0; ks < 2; ks++) {
            int k0 = ks * 8;
            unsigned a[4][4], bf[8][2];
            #pragma unroll
            for (int mt = 0; mt < 4; mt++) {
                int r = wm + mt * 16;
                a[mt][0] = __float_as_uint(Ac[(r + g)*20 + k0 + t]);
                a[mt][1] = __float_as_uint(Ac[(r + 8 + g)*20 + k0 + t]);
                a[mt][2] = __float_as_uint(Ac[(r + g)*20 + k0 + t + 4]);
                a[mt][3] = __float_as_uint(Ac[(r + 8 + g)*20 + k0 + t + 4]);
            }
            #pragma unroll
            for (int nt = 0; nt < 8; nt++) {
                int c = wn + nt * 8 + g;
                bf[nt][0] = __float_as_uint(Bc[(k0 + t)*136 + c]);
                bf[nt][1] = __float_as_uint(Bc[(k0 + t + 4)*136 + c]);
            }
            #pragma unroll
            for (int mt = 0; mt < 4; mt++)
                #pragma unroll
                for (int nt = 0; nt < 8; nt++)
                    mma8(acc[mt][nt], a[mt], bf[nt]);
        }
    }

    #pragma unroll
    for (int mt = 0; mt < 4; mt++)
        #pragma unroll
        for (int nt = 0; nt < 8; nt++) {
            int r = bm + wm + mt * 16 + g;
            int c = bn + wn + nt * 8 + 2 * t;
            *(float2*)&C[(size_t)r * N + c] =
                make_float2(alpha * acc[mt][nt][0], alpha * acc[mt][nt][1]);
            *(float2*)&C[(size_t)(r + 8) * N + c] =
                make_float2(alpha * acc[mt][nt][2], alpha * acc[mt][nt][3]);
        }
}

__global__ __launch_bounds__(128, 2) void proj4_kernel(const float* __restrict__ x,
    const float* __restrict__ W, float* Qo, float* Ko, float* Vo, float* Go)
{
    const float* Bp; float* Cp; float alpha = 1.f;
    switch (blockIdx.z) {
        case 0:  Bp = W;             Cp = Qo; alpha = 0.125f; break;
        case 1:  Bp = W + DD*DD;     Cp = Ko; break;
        case 2:  Bp = W + 2*DD*DD;   Cp = Vo; break;
        default: Bp = W + 3*DD*DD;   Cp = Go; break;
    }
    gemm_body(x, Bp, Cp, MT, DD, DD, alpha);
}

__global__ __launch_bounds__(128, 2) void gemm_kernel(const float* __restrict__ A,
                                                      const float* __restrict__ B,
                                                      float* __restrict__ C)
{
    gemm_body(A, B, C, MT, DD, DD, 1.f);
}

// ============================================================
// Chunkwise retention (tf32 mma).
// ============================================================
#define QSTR 68
#define KSTR 76

__global__ __launch_bounds__(256) void chunk_outer(const float* __restrict__ K,
                                                   const float* __restrict__ V,
                                                   float* __restrict__ Bout)
{
    __shared__ float Ks[64 * KSTR];
    __shared__ float Vd[64 * KSTR];

    int c = blockIdx.x, h = blockIdx.y, b = blockIdx.z;
    int tid = threadIdx.x;
    int w = tid >> 5, lane = tid & 31;
    int g = lane >> 2, t = lane & 3;
    int wi = (w >> 2) * 32, wj = (w & 3) * 16;

    float log2g = log2f(1.f - exp2f(-5.f - (float)h));

    int lr = tid >> 2, lc = (tid & 3) * 4;
    const float* Kb = K + ((size_t)b * TT + (size_t)c * CS) * DD + h * DH;
    const float* Vb = V + ((size_t)b * TT + (size_t)c * CS) * DD + h * DH;
    float dec = exp2f(log2g * (float)(CS - lr));

    #pragma unroll
    for (int p = 0; p < 4; p++) {
        int c0 = lc + p * 16;
        float4 kv = *(const float4*)&Kb[(size_t)lr * DD + c0];
        Ks[(c0 + 0) * KSTR + lr] = f2tf(kv.x);
        Ks[(c0 + 1) * KSTR + lr] = f2tf(kv.y);
        Ks[(c0 + 2) * KSTR + lr] = f2tf(kv.z);
        Ks[(c0 + 3) * KSTR + lr] = f2tf(kv.w);
        float4 vv = *(const float4*)&Vb[(size_t)lr * DD + c0];
        float4 vd = make_float4(f2tf(dec * vv.x), f2tf(dec * vv.y),
                                f2tf(dec * vv.z), f2tf(dec * vv.w));
        *(float4*)&Vd[lr * KSTR + c0] = vd;
    }
    __syncthreads();

    float bacc[2][2][4];
    #pragma unroll
    for (int i = 0; i < 2; i++)
        #pragma unroll
        for (int j = 0; j < 2; j++)
            #pragma unroll
            for (int q = 0; q < 4; q++) bacc[i][j][q] = 0.f;

    #pragma unroll
    for (int j8 = 0; j8 < 8; j8++) {
        int k0 = j8 * 8;
        unsigned a[2][4], bf[2][2];
        #pragma unroll
        for (int mt = 0; mt < 2; mt++) {
            int r = wi + mt * 16;
            a[mt][0] = __float_as_uint(Ks[(r + g) * KSTR + k0 + t]);
            a[mt][1] = __float_as_uint(Ks[(r + 8 + g) * KSTR + k0 + t]);
            a[mt][2] = __float_as_uint(Ks[(r + g) * KSTR + k0 + t + 4]);
            a[mt][3] = __float_as_uint(Ks[(r + 8 + g) * KSTR + k0 + t + 4]);
        }
        #pragma unroll
        for (int nt = 0; nt < 2; nt++) {
            int cc = wj + nt * 8 + g;
            bf[nt][0] = __float_as_uint(Vd[(k0 + t) * KSTR + cc]);
            bf[nt][1] = __float_as_uint(Vd[(k0 + t + 4) * KSTR + cc]);
        }
        #pragma unroll
        for (int mt = 0; mt < 2; mt++)
            #pragma unroll
            for (int nt = 0; nt < 2; nt++)
                mma8(bacc[mt][nt], a[mt], bf[nt]);
    }

    size_t base = (((size_t)(b * HH + h)) * NC + c) * (DH * DH);
    #pragma unroll
    for (int mt = 0; mt < 2; mt++)
        #pragma unroll
        for (int nt = 0; nt < 2; nt++) {
            int r = wi + mt * 16 + g;
            int cc = wj + nt * 8 + 2 * t;
            *(float2*)&Bout[base + r * DH + cc] = make_float2(bacc[mt][nt][0], bacc[mt][nt][1]);
            *(float2*)&Bout[base + (r + 8) * DH + cc] = make_float2(bacc[mt][nt][2], bacc[mt][nt][3]);
        }
}

__global__ __launch_bounds__(256) void scan_state(const float* __restrict__ Bm,
                                                  float* __restrict__ Sm)
{
    int bh = blockIdx.x;
    int part = blockIdx.y;
    int h = bh & 7;
    float log2g = log2f(1.f - exp2f(-5.f - (float)h));
    float gc = exp2f(64.f * log2g);

    size_t base = (size_t)bh * NC * (DH * DH) + part * 512 + threadIdx.x;
    float s0 = 0.f, s1 = 0.f;
    for (int c = 0; c < NC; c++) {
        size_t o = base + (size_t)c * (DH * DH);
        Sm[o] = s0;        s0 = gc * s0 + Bm[o];
        Sm[o + 256] = s1;  s1 = gc * s1 + Bm[o + 256];
    }
}

#define RET_SMEM ((2*64*QSTR + 3*64*KSTR) * 4)

__global__ __launch_bounds__(256) void retention_chunk(
    const float* __restrict__ Q, const float* __restrict__ K,
    const float* __restrict__ V, const float* __restrict__ Sm,
    const float* __restrict__ G, const float* __restrict__ gnw,
    const float* __restrict__ gnb, float* __restrict__ Y)
{
    extern __shared__ float sm[];
    float* Qs = sm;
    float* Ss = Qs + 64 * QSTR;
    float* Ks = Ss + 64 * QSTR;
    float* Vd = Ks + 64 * KSTR;
    float* Ts = Vd + 64 * KSTR;

    int c = blockIdx.x, h = blockIdx.y, b = blockIdx.z;
    int tid = threadIdx.x;
    int w = tid >> 5, lane = tid & 31;
    int g = lane >> 2, t = lane & 3;
    int wi = (w >> 2) * 32, wj = (w & 3) * 16;

    float log2g = log2f(1.f - exp2f(-5.f - (float)h));

    int lr = tid >> 2, lc = (tid & 3) * 4;
    const float* Qb = Q + ((size_t)b * TT + (size_t)c * CS) * DD + h * DH;
    const float* Kb = K + ((size_t)b * TT + (size_t)c * CS) * DD + h * DH;
    const float* Vb = V + ((size_t)b * TT + (size_t)c * CS) * DD + h * DH;
    const float* Tb = Sm + (((size_t)(b * HH + h)) * NC + c) * (DH * DH);
    float dec = exp2f(log2g * (float)(CS - lr));

    #pragma unroll
    for (int p = 0; p < 4; p++) {
        int c0 = lc + p * 16;
        float4 qv = *(const float4*)&Qb[(size_t)lr * DD + c0];
        Qs[lr * QSTR + c0 + 0] = f2tf(qv.x);
        Qs[lr * QSTR + c0 + 1] = f2tf(qv.y);
        Qs[lr * QSTR + c0 + 2] = f2tf(qv.z);
        Qs[lr * QSTR + c0 + 3] = f2tf(qv.w);
        float4 kv = *(const float4*)&Kb[(size_t)lr * DD + c0];
        Ks[(c0 + 0) * KSTR + lr] = f2tf(kv.x);
        Ks[(c0 + 1) * KSTR + lr] = f2tf(kv.y);
        Ks[(c0 + 2) * KSTR + lr] = f2tf(kv.z);
        Ks[(c0 + 3) * KSTR + lr] = f2tf(kv.w);
        float4 vv = *(const float4*)&Vb[(size_t)lr * DD + c0];
        float4 vd = make_float4(f2tf(dec * vv.x), f2tf(dec * vv.y),
                                f2tf(dec * vv.z), f2tf(dec * vv.w));
        *(float4*)&Vd[lr * KSTR + c0] = vd;
        float4 tv = *(const float4*)&Tb[lr * DH + c0];
        float4 td = make_float4(f2tf(tv.x), f2tf(tv.y), f2tf(tv.z), f2tf(tv.w));
        *(float4*)&Ts[lr * KSTR + c0] = td;
    }
    __syncthreads();

    float sacc[2][2][4], iacc[2][2][4];
    #pragma unroll
    for (int i = 0; i < 2; i++)
        #pragma unroll
        for (int j = 0; j < 2; j++)
            #pragma unroll
            for (int q = 0; q < 4; q++) { sacc[i][j][q] = 0.f; iacc[i][j][q] = 0.f; }

    #pragma unroll
    for (int d8 = 0; d8 < 8; d8++) {
        int k0 = d8 * 8;
        unsigned a[2][4], bk_[2][2], bt[2][2];
        #pragma unroll
        for (int mt = 0; mt < 2; mt++) {
            int r = wi + mt * 16;
            a[mt][0] = __float_as_uint(Qs[(r + g) * QSTR + k0 + t]);
            a[mt][1] = __float_as_uint(Qs[(r + 8 + g) * QSTR + k0 + t]);
            a[mt][2] = __float_as_uint(Qs[(r + g) * QSTR + k0 + t + 4]);
            a[mt][3] = __float_as_uint(Qs[(r + 8 + g) * QSTR + k0 + t + 4]);
        }
        #pragma unroll
        for (int nt = 0; nt < 2; nt++) {
            int cc = wj + nt * 8 + g;
            bk_[nt][0] = __float_as_uint(Ks[(k0 + t) * KSTR + cc]);
            bk_[nt][1] = __float_as_uint(Ks[(k0 + t + 4) * KSTR + cc]);
            bt[nt][0] = __float_as_uint(Ts[(k0 + t) * KSTR + cc]);
            bt[nt][1] = __float_as_uint(Ts[(k0 + t + 4) * KSTR + cc]);
        }
        #pragma unroll
        for (int mt = 0; mt < 2; mt++)
            #pragma unroll
            for (int nt = 0; nt < 2; nt++) {
                mma8(sacc[mt][nt], a[mt], bk_[nt]);
                mma8(iacc[mt][nt], a[mt], bt[nt]);
            }
    }

    #pragma unroll
    for (int mt = 0; mt < 2; mt++) {
        #pragma unroll
        for (int nt = 0; nt < 2; nt++) {
            int r0 = wi + mt * 16 + g;
            int c0 = wj + nt * 8 + 2 * t;
            #pragma unroll
            for (int e = 0; e < 4; e++) {
                int r = r0 + (e >> 1) * 8;
                int cc = c0 + (e & 1);
                float wgt = (r >= cc) ? exp2f(log2g * (float)(r - 64)) : 0.f;
                Ss[r * QSTR + cc] = f2tf(sacc[mt][nt][e] * wgt);
            }
        }
    }
    __syncthreads();

    float oacc[2][2][4];
    #pragma unroll
    for (int i = 0; i < 2; i++)
        #pragma unroll
        for (int j = 0; j < 2; j++)
            #pragma unroll
            for (int q = 0; q < 4; q++) oacc[i][j][q] = 0.f;

    #pragma unroll
    for (int m8 = 0; m8 < 8; m8++) {
        int k0 = m8 * 8;
        unsigned a[2][4], bf[2][2];
        #pragma unroll
        for (int mt = 0; mt < 2; mt++) {
            int r = wi + mt * 16;
            a[mt][0] = __float_as_uint(Ss[(r + g) * QSTR + k0 + t]);
            a[mt][1] = __float_as_uint(Ss[(r + 8 + g) * QSTR + k0 + t]);
            a[mt][2] = __float_as_uint(Ss[(r + g) * QSTR + k0 + t + 4]);
            a[mt][3] = __float_as_uint(Ss[(r + 8 + g) * QSTR + k0 + t + 4]);
        }
        #pragma unroll
        for (int nt = 0; nt < 2; nt++) {
            int cc = wj + nt * 8 + g;
            bf[nt][0] = __float_as_uint(Vd[(k0 + t) * KSTR + cc]);
            bf[nt][1] = __float_as_uint(Vd[(k0 + t + 4) * KSTR + cc]);
        }
        #pragma unroll
        for (int mt = 0; mt < 2; mt++)
            #pragma unroll
            for (int nt = 0; nt < 2; nt++)
                mma8(oacc[mt][nt], a[mt], bf[nt]);
    }
    __syncthreads();

    #pragma unroll
    for (int mt = 0; mt < 2; mt++) {
        #pragma unroll
        for (int nt = 0; nt < 2; nt++) {
            int r0 = wi + mt * 16 + g;
            int c0 = wj + nt * 8 + 2 * t;
            float scA = exp2f(log2g * (float)r0);
            float scB = exp2f(log2g * (float)(r0 + 8));
            Ss[r0 * QSTR + c0]           = oacc[mt][nt][0] + scA * iacc[mt][nt][0];
            Ss[r0 * QSTR + c0 + 1]       = oacc[mt][nt][1] + scA * iacc[mt][nt][1];
            Ss[(r0 + 8) * QSTR + c0]     = oacc[mt][nt][2] + scB * iacc[mt][nt][2];
            Ss[(r0 + 8) * QSTR + c0 + 1] = oacc[mt][nt][3] + scB * iacc[mt][nt][3];
        }
    }
    __syncthreads();

    // GroupNorm + SiLU gate; store Y tf32-converted for the output GEMM
    int tok = tid >> 2, sub = tid & 3;
    float vals[16];
    float s = 0.f, sq = 0.f;
    #pragma unroll
    for (int u = 0; u < 16; u++) {
        float v = Ss[tok * QSTR + sub * 16 + u];
        vals[u] = v; s += v; sq += v * v;
    }
    s  += __shfl_xor_sync(0xffffffffu, s, 1);
    s  += __shfl_xor_sync(0xffffffffu, s, 2);
    sq += __shfl_xor_sync(0xffffffffu, sq, 1);
    sq += __shfl_xor_sync(0xffffffffu, sq, 2);
    float mean = s * (1.f / 64.f);
    float inv = rsqrtf(sq * (1.f / 64.f) - mean * mean + 1e-5f);

    size_t row = (size_t)b * TT + (size_t)c * CS + tok;
    int wcol = h * DH + sub * 16;
    const float* gp = G + row * DD + wcol;
    float* yp = Y + row * DD + wcol;
    #pragma unroll
    for (int u4 = 0; u4 < 4; u4++) {
        float4 wv = *(const float4*)&gnw[wcol + u4 * 4];
        float4 bv = *(const float4*)&gnb[wcol + u4 * 4];
        float4 gv = *(const float4*)&gp[u4 * 4];
        float4 yv;
        float z;
        z = gv.x + (vals[u4*4+0] - mean) * inv * wv.x + bv.x; yv.x = f2tf(z / (1.f + expf(-z)));
        z = gv.y + (vals[u4*4+1] - mean) * inv * wv.y + bv.y; yv.y = f2tf(z / (1.f + expf(-z)));
        z = gv.z + (vals[u4*4+2] - mean) * inv * wv.z + bv.z; yv.z = f2tf(z / (1.f + expf(-z)));
        z = gv.w + (vals[u4*4+3] - mean) * inv * wv.w + bv.w; yv.w = f2tf(z / (1.f + expf(-z)));
        *(float4*)&yp[u4 * 4] = yv;
    }
}

// ============================================================
extern "C" void kernel_launch(void* const* d_in, const int* in_sizes, int n_in,
                              void* d_out, int out_size) {
    const float* x   = (const float*)d_in[0];
    const float* WQ  = (const float*)d_in[1];
    const float* WK  = (const float*)d_in[2];
    const float* WV  = (const float*)d_in[3];
    const float* WG  = (const float*)d_in[4];
    const float* WO  = (const float*)d_in[5];
    const float* gnw = (const float*)d_in[6];
    const float* gnb = (const float*)d_in[7];
    float* out = (float*)d_out;

    float *Xp, *Wp, *Qp, *Kp, *Vp, *Gp, *Yp, *Bp, *Sp;
    cudaGetSymbolAddress((void**)&Xp, g_X);
    cudaGetSymbolAddress((void**)&Wp, g_W5);
    cudaGetSymbolAddress((void**)&Qp, g_Q);
    cudaGetSymbolAddress((void**)&Kp, g_K);
    cudaGetSymbolAddress((void**)&Vp, g_V);
    cudaGetSymbolAddress((void**)&Gp, g_G);
    cudaGetSymbolAddress((void**)&Yp, g_Y);
    cudaGetSymbolAddress((void**)&Bp, g_B);
    cudaGetSymbolAddress((void**)&Sp, g_S);

    cudaFuncSetAttribute(proj4_kernel,
                         cudaFuncAttributeMaxDynamicSharedMemorySize, GEMM_SMEM);
    cudaFuncSetAttribute(gemm_kernel,
                         cudaFuncAttributeMaxDynamicSharedMemorySize, GEMM_SMEM);
    cudaFuncSetAttribute(retention_chunk,
                         cudaFuncAttributeMaxDynamicSharedMemorySize, RET_SMEM);

    conv_tf32<<<dim3(2048, 1, 6), 256>>>(x, WQ, WK, WV, WG, WO, Xp, Wp);

    proj4_kernel<<<dim3(DD / 128, MT / 128, 4), 128, GEMM_SMEM>>>(
        Xp, Wp, Qp, Kp, Vp, Gp);

    chunk_outer<<<dim3(NC, HH, BB), 256>>>(Kp, Vp, Bp);

    scan_state<<<dim3(BB * HH, 8), 256>>>(Bp, Sp);

    retention_chunk<<<dim3(NC, HH, BB), 256, RET_SMEM>>>(Qp, Kp, Vp, Sp,
                                                         Gp, gnw, gnb, Yp);

    gemm_kernel<<<dim3(DD / 128, MT / 128, 1), 128, GEMM_SMEM>>>(
        Yp, Wp + 4 * DD * DD, out);
}

// round 8
// speedup vs baseline: 7.3126x; 1.2134x over previous
#include <cuda_runtime.h>
#include <cuda_fp16.h>
#include <math.h>

#define BB 2
#define TT 2048
#define DD 512
#define HH 8
#define DH 64
#define MT (BB*TT)   // 4096
#define NC 32
#define CS 64

// ---- scratch (static device globals; no allocation) ----
__device__ __half g_Xh[MT*DD];
__device__ __half g_W5h[5*DD*DD];
__device__ __half g_Yh[MT*DD];
__device__ float g_Q[MT*DD];
__device__ float g_K[MT*DD];
__device__ float g_V[MT*DD];
__device__ float g_G[MT*DD];
__device__ float g_B[BB*HH*NC*DH*DH];
__device__ float g_S[BB*HH*NC*DH*DH];

// ---- helpers ----
__device__ __forceinline__ float f2tf(float x) {
    unsigned u;
    asm("cvt.rna.tf32.f32 %0, %1;" : "=r"(u) : "f"(x));
    return __uint_as_float(u);
}
__device__ __forceinline__ void mma8(float* c, const unsigned* a, const unsigned* b) {
    asm volatile("mma.sync.aligned.m16n8k8.row.col.f32.tf32.tf32.f32 "
        "{%0,%1,%2,%3}, {%4,%5,%6,%7}, {%8,%9}, {%0,%1,%2,%3};\n"
        : "+f"(c[0]), "+f"(c[1]), "+f"(c[2]), "+f"(c[3])
        : "r"(a[0]), "r"(a[1]), "r"(a[2]), "r"(a[3]), "r"(b[0]), "r"(b[1]));
}
__device__ __forceinline__ void mma16(float* c, const unsigned* a, const unsigned* b) {
    asm volatile("mma.sync.aligned.m16n8k16.row.col.f32.f16.f16.f32 "
        "{%0,%1,%2,%3}, {%4,%5,%6,%7}, {%8,%9}, {%0,%1,%2,%3};\n"
        : "+f"(c[0]), "+f"(c[1]), "+f"(c[2]), "+f"(c[3])
        : "r"(a[0]), "r"(a[1]), "r"(a[2]), "r"(a[3]), "r"(b[0]), "r"(b[1]));
}
__device__ __forceinline__ void ldmA4(unsigned* r, unsigned addr) {
    asm volatile("ldmatrix.sync.aligned.m8n8.x4.shared.b16 {%0,%1,%2,%3}, [%4];"
        : "=r"(r[0]), "=r"(r[1]), "=r"(r[2]), "=r"(r[3]) : "r"(addr));
}
__device__ __forceinline__ void ldmB4T(unsigned* r, unsigned addr) {
    asm volatile("ldmatrix.sync.aligned.m8n8.x4.trans.shared.b16 {%0,%1,%2,%3}, [%4];"
        : "=r"(r[0]), "=r"(r[1]), "=r"(r[2]), "=r"(r[3]) : "r"(addr));
}
__device__ __forceinline__ void cp16h(__half* smem, const __half* g) {
    unsigned s = (unsigned)__cvta_generic_to_shared(smem);
    asm volatile("cp.async.cg.shared.global [%0], [%1], 16;\n" :: "r"(s), "l"(g));
}
#define CP_COMMIT() asm volatile("cp.async.commit_group;\n" ::: "memory")
#define CP_WAIT1()  asm volatile("cp.async.wait_group 1;\n" ::: "memory")

// ============================================================
// fp16 pre-conversion of x and the five weights.
// ============================================================
__global__ __launch_bounds__(256) void conv_half(
    const float* __restrict__ x,
    const float* __restrict__ w0, const float* __restrict__ w1,
    const float* __restrict__ w2, const float* __restrict__ w3,
    const float* __restrict__ w4,
    __half* __restrict__ xo, __half* __restrict__ wo)
{
    int z = blockIdx.z;
    if (z == 0) {
        int i = blockIdx.x * 256 + threadIdx.x;   // 524288 float4
        float4 v = ((const float4*)x)[i];
        __half2* d = (__half2*)xo;
        d[2*i]   = __floats2half2_rn(v.x, v.y);
        d[2*i+1] = __floats2half2_rn(v.z, v.w);
    } else {
        if (blockIdx.x >= 256) return;            // 65536 float4 per weight
        const float* s = (z==1)?w0:(z==2)?w1:(z==3)?w2:(z==4)?w3:w4;
        __half2* d = (__half2*)(wo + (size_t)(z-1) * DD * DD);
        int i = blockIdx.x * 256 + threadIdx.x;
        float4 v = ((const float4*)s)[i];
        d[2*i]   = __floats2half2_rn(v.x, v.y);
        d[2*i+1] = __floats2half2_rn(v.z, v.w);
    }
}

// ============================================================
// fp16 GEMM: C = alpha * A @ B (fp32 accum/output).
// CTA 128x128, 4 warps of 64x64, BK=32, 3-stage cp.async,
// ldmatrix operand loads.
// ============================================================
#define AS 40               // halves per A smem row (pad: conflict-free)
#define BS 136              // halves per B smem row
#define HAS (128*AS)        // 5120 halves / stage
#define HBS (32*BS)         // 4352 halves / stage
#define GEMM_SMEM (3*(HAS+HBS)*2)   // 56832 bytes

__device__ __forceinline__ void gemm_body_h(const __half* __restrict__ A,
                                            const __half* __restrict__ B,
                                            float* __restrict__ C,
                                            int M, int N, int K, float alpha)
{
    extern __shared__ __half smh[];
    __half* Asm = smh;
    __half* Bsm = smh + 3*HAS;

    int tid = threadIdx.x;               // 0..127
    int w = tid >> 5, lane = tid & 31;
    int g = lane >> 2, t = lane & 3;
    int wm = (w >> 1) * 64;
    int wn = (w & 1) * 64;
    int bm = blockIdx.y * 128, bn = blockIdx.x * 128;

    int ar = tid;                        // one A row per thread
    int bkr = tid >> 2, bq = (tid & 3) * 32;

    const __half* Ag = A + (size_t)(bm + ar) * K;
    const __half* Bg = B + (size_t)bkr * N + bn + bq;

    float acc[4][8][4];
    #pragma unroll
    for (int i = 0; i < 4; i++)
        #pragma unroll
        for (int j = 0; j < 8; j++)
            #pragma unroll
            for (int q = 0; q < 4; q++) acc[i][j][q] = 0.f;

    int ntile = K >> 5;   // BK=32

    #pragma unroll
    for (int p = 0; p < 2; p++) {
        #pragma unroll
        for (int i = 0; i < 4; i++) {
            cp16h(&Asm[p*HAS + ar*AS + 8*i], Ag + p*32 + 8*i);
            cp16h(&Bsm[p*HBS + bkr*BS + bq + 8*i], Bg + (size_t)(p*32) * N + 8*i);
        }
        CP_COMMIT();
    }

    int lrow = lane & 15, lcol = (lane >> 4) << 3;

    for (int kt = 0; kt < ntile; kt++) {
        int cur = kt % 3;
        CP_WAIT1();
        __syncthreads();

        if (kt + 2 < ntile) {
            int s = (kt + 2) % 3;
            int off = (kt + 2) * 32;
            #pragma unroll
            for (int i = 0; i < 4; i++) {
                cp16h(&Asm[s*HAS + ar*AS + 8*i], Ag + off + 8*i);
                cp16h(&Bsm[s*HBS + bkr*BS + bq + 8*i], Bg + (size_t)off * N + 8*i);
            }
        }
        CP_COMMIT();

        unsigned abase = (unsigned)__cvta_generic_to_shared(Asm + cur*HAS)
                       + ((wm + lrow) * AS + lcol) * 2;
        unsigned bbase = (unsigned)__cvta_generic_to_shared(Bsm + cur*HBS)
                       + (lrow * BS + wn + lcol) * 2;

        #pragma unroll
        for (int ks = 0; ks < 2; ks++) {
            int k0 = ks * 16;
            unsigned a[4][4], bf[4][4];
            #pragma unroll
            for (int mt = 0; mt < 4; mt++)
                ldmA4(a[mt], abase + (mt*16*AS + k0) * 2);
            #pragma unroll
            for (int n2 = 0; n2 < 4; n2++)
                ldmB4T(bf[n2], bbase + (k0*BS + n2*16) * 2);
            #pragma unroll
            for (int mt = 0; mt < 4; mt++)
                #pragma unroll
                for (int nt = 0; nt < 8; nt++)
                    mma16(acc[mt][nt], a[mt], &bf[nt >> 1][(nt & 1) * 2]);
        }
    }

    #pragma unroll
    for (int mt = 0; mt < 4; mt++)
        #pragma unroll
        for (int nt = 0; nt < 8; nt++) {
            int r = bm + wm + mt * 16 + g;
            int c = bn + wn + nt * 8 + 2 * t;
            *(float2*)&C[(size_t)r * N + c] =
                make_float2(alpha * acc[mt][nt][0], alpha * acc[mt][nt][1]);
            *(float2*)&C[(size_t)(r + 8) * N + c] =
                make_float2(alpha * acc[mt][nt][2], alpha * acc[mt][nt][3]);
        }
}

__global__ __launch_bounds__(128, 2) void proj4_kernel(const __half* __restrict__ x,
    const __half* __restrict__ W, float* Qo, float* Ko, float* Vo, float* Go)
{
    const __half* Bp; float* Cp; float alpha = 1.f;
    switch (blockIdx.z) {
        case 0:  Bp = W;             Cp = Qo; alpha = 0.125f; break;
        case 1:  Bp = W + DD*DD;     Cp = Ko; break;
        case 2:  Bp = W + 2*DD*DD;   Cp = Vo; break;
        default: Bp = W + 3*DD*DD;   Cp = Go; break;
    }
    gemm_body_h(x, Bp, Cp, MT, DD, DD, alpha);
}

__global__ __launch_bounds__(128, 2) void gemm_kernel(const __half* __restrict__ A,
                                                      const __half* __restrict__ B,
                                                      float* __restrict__ C)
{
    gemm_body_h(A, B, C, MT, DD, DD, 1.f);
}

// ============================================================
// Chunkwise retention (tf32 mma).
// ============================================================
#define QSTR 68
#define KSTR 76

__global__ __launch_bounds__(256) void chunk_outer(const float* __restrict__ K,
                                                   const float* __restrict__ V,
                                                   float* __restrict__ Bout)
{
    __shared__ float Ks[64 * KSTR];
    __shared__ float Vd[64 * KSTR];

    int c = blockIdx.x, h = blockIdx.y, b = blockIdx.z;
    int tid = threadIdx.x;
    int w = tid >> 5, lane = tid & 31;
    int g = lane >> 2, t = lane & 3;
    int wi = (w >> 2) * 32, wj = (w & 3) * 16;

    float log2g = log2f(1.f - exp2f(-5.f - (float)h));

    int lr = tid >> 2, lc = (tid & 3) * 4;
    const float* Kb = K + ((size_t)b * TT + (size_t)c * CS) * DD + h * DH;
    const float* Vb = V + ((size_t)b * TT + (size_t)c * CS) * DD + h * DH;
    float dec = exp2f(log2g * (float)(CS - lr));

    #pragma unroll
    for (int p = 0; p < 4; p++) {
        int c0 = lc + p * 16;
        float4 kv = *(const float4*)&Kb[(size_t)lr * DD + c0];
        Ks[(c0 + 0) * KSTR + lr] = f2tf(kv.x);
        Ks[(c0 + 1) * KSTR + lr] = f2tf(kv.y);
        Ks[(c0 + 2) * KSTR + lr] = f2tf(kv.z);
        Ks[(c0 + 3) * KSTR + lr] = f2tf(kv.w);
        float4 vv = *(const float4*)&Vb[(size_t)lr * DD + c0];
        float4 vd = make_float4(f2tf(dec * vv.x), f2tf(dec * vv.y),
                                f2tf(dec * vv.z), f2tf(dec * vv.w));
        *(float4*)&Vd[lr * KSTR + c0] = vd;
    }
    __syncthreads();

    float bacc[2][2][4];
    #pragma unroll
    for (int i = 0; i < 2; i++)
        #pragma unroll
        for (int j = 0; j < 2; j++)
            #pragma unroll
            for (int q = 0; q < 4; q++) bacc[i][j][q] = 0.f;

    #pragma unroll
    for (int j8 = 0; j8 < 8; j8++) {
        int k0 = j8 * 8;
        unsigned a[2][4], bf[2][2];
        #pragma unroll
        for (int mt = 0; mt < 2; mt++) {
            int r = wi + mt * 16;
            a[mt][0] = __float_as_uint(Ks[(r + g) * KSTR + k0 + t]);
            a[mt][1] = __float_as_uint(Ks[(r + 8 + g) * KSTR + k0 + t]);
            a[mt][2] = __float_as_uint(Ks[(r + g) * KSTR + k0 + t + 4]);
            a[mt][3] = __float_as_uint(Ks[(r + 8 + g) * KSTR + k0 + t + 4]);
        }
        #pragma unroll
        for (int nt = 0; nt < 2; nt++) {
            int cc = wj + nt * 8 + g;
            bf[nt][0] = __float_as_uint(Vd[(k0 + t) * KSTR + cc]);
            bf[nt][1] = __float_as_uint(Vd[(k0 + t + 4) * KSTR + cc]);
        }
        #pragma unroll
        for (int mt = 0; mt < 2; mt++)
            #pragma unroll
            for (int nt = 0; nt < 2; nt++)
                mma8(bacc[mt][nt], a[mt], bf[nt]);
    }

    size_t base = (((size_t)(b * HH + h)) * NC + c) * (DH * DH);
    #pragma unroll
    for (int mt = 0; mt < 2; mt++)
        #pragma unroll
        for (int nt = 0; nt < 2; nt++) {
            int r = wi + mt * 16 + g;
            int cc = wj + nt * 8 + 2 * t;
            *(float2*)&Bout[base + r * DH + cc] = make_float2(bacc[mt][nt][0], bacc[mt][nt][1]);
            *(float2*)&Bout[base + (r + 8) * DH + cc] = make_float2(bacc[mt][nt][2], bacc[mt][nt][3]);
        }
}

// K2a: scan over chunks — batch independent loads, register prefix.
__global__ __launch_bounds__(256) void scan_state(const float* __restrict__ Bm,
                                                  float* __restrict__ Sm)
{
    int bh = blockIdx.x;          // 0..15
    int h = bh & 7;
    float log2g = log2f(1.f - exp2f(-5.f - (float)h));
    float gc = exp2f(64.f * log2g);

    int e = blockIdx.y * 256 + threadIdx.x;   // 0..4095
    size_t base = (size_t)bh * NC * (DH * DH) + e;

    float v[NC];
    #pragma unroll
    for (int c = 0; c < NC; c++) v[c] = Bm[base + (size_t)c * (DH * DH)];
    float s = 0.f;
    #pragma unroll
    for (int c = 0; c < NC; c++) {
        Sm[base + (size_t)c * (DH * DH)] = s;
        s = gc * s + v[c];
    }
}

// K2b: intra + inter + GroupNorm + SiLU gate (Q pre-scaled by 1/8).
#define RET_BODY (2*64*QSTR + 3*64*KSTR)
#define RET_SMEM ((RET_BODY + 65 + 64) * 4)

__global__ __launch_bounds__(256) void retention_chunk(
    const float* __restrict__ Q, const float* __restrict__ K,
    const float* __restrict__ V, const float* __restrict__ Sm,
    const float* __restrict__ G, const float* __restrict__ gnw,
    const float* __restrict__ gnb, __half* __restrict__ Y)
{
    extern __shared__ float sm[];
    float* Qs = sm;
    float* Ss = Qs + 64 * QSTR;
    float* Ks = Ss + 64 * QSTR;
    float* Vd = Ks + 64 * KSTR;
    float* Ts = Vd + 64 * KSTR;
    float* gp = sm + RET_BODY;        // gamma^i, i=0..64
    float* gn = gp + 65;              // gamma^(i-64), i=0..63

    int c = blockIdx.x, h = blockIdx.y, b = blockIdx.z;
    int tid = threadIdx.x;
    int w = tid >> 5, lane = tid & 31;
    int g = lane >> 2, t = lane & 3;
    int wi = (w >> 2) * 32, wj = (w & 3) * 16;

    float log2g = log2f(1.f - exp2f(-5.f - (float)h));

    if (tid < 65) gp[tid] = exp2f(log2g * (float)tid);
    if (tid < 64) gn[tid] = exp2f(log2g * (float)(tid - 64));

    int lr = tid >> 2, lc = (tid & 3) * 4;
    const float* Qb = Q + ((size_t)b * TT + (size_t)c * CS) * DD + h * DH;
    const float* Kb = K + ((size_t)b * TT + (size_t)c * CS) * DD + h * DH;
    const float* Vb = V + ((size_t)b * TT + (size_t)c * CS) * DD + h * DH;
    const float* Tb = Sm + (((size_t)(b * HH + h)) * NC + c) * (DH * DH);
    float dec = exp2f(log2g * (float)(CS - lr));

    #pragma unroll
    for (int p = 0; p < 4; p++) {
        int c0 = lc + p * 16;
        float4 qv = *(const float4*)&Qb[(size_t)lr * DD + c0];
        Qs[lr * QSTR + c0 + 0] = f2tf(qv.x);
        Qs[lr * QSTR + c0 + 1] = f2tf(qv.y);
        Qs[lr * QSTR + c0 + 2] = f2tf(qv.z);
        Qs[lr * QSTR + c0 + 3] = f2tf(qv.w);
        float4 kv = *(const float4*)&Kb[(size_t)lr * DD + c0];
        Ks[(c0 + 0) * KSTR + lr] = f2tf(kv.x);
        Ks[(c0 + 1) * KSTR + lr] = f2tf(kv.y);
        Ks[(c0 + 2) * KSTR + lr] = f2tf(kv.z);
        Ks[(c0 + 3) * KSTR + lr] = f2tf(kv.w);
        float4 vv = *(const float4*)&Vb[(size_t)lr * DD + c0];
        float4 vd = make_float4(f2tf(dec * vv.x), f2tf(dec * vv.y),
                                f2tf(dec * vv.z), f2tf(dec * vv.w));
        *(float4*)&Vd[lr * KSTR + c0] = vd;
        float4 tv = *(const float4*)&Tb[lr * DH + c0];
        float4 td = make_float4(f2tf(tv.x), f2tf(tv.y), f2tf(tv.z), f2tf(tv.w));
        *(float4*)&Ts[lr * KSTR + c0] = td;
    }
    __syncthreads();

    float sacc[2][2][4], iacc[2][2][4];
    #pragma unroll
    for (int i = 0; i < 2; i++)
        #pragma unroll
        for (int j = 0; j < 2; j++)
            #pragma unroll
            for (int q = 0; q < 4; q++) { sacc[i][j][q] = 0.f; iacc[i][j][q] = 0.f; }

    #pragma unroll
    for (int d8 = 0; d8 < 8; d8++) {
        int k0 = d8 * 8;
        unsigned a[2][4], bk_[2][2], bt[2][2];
        #pragma unroll
        for (int mt = 0; mt < 2; mt++) {
            int r = wi + mt * 16;
            a[mt][0] = __float_as_uint(Qs[(r + g) * QSTR + k0 + t]);
            a[mt][1] = __float_as_uint(Qs[(r + 8 + g) * QSTR + k0 + t]);
            a[mt][2] = __float_as_uint(Qs[(r + g) * QSTR + k0 + t + 4]);
            a[mt][3] = __float_as_uint(Qs[(r + 8 + g) * QSTR + k0 + t + 4]);
        }
        #pragma unroll
        for (int nt = 0; nt < 2; nt++) {
            int cc = wj + nt * 8 + g;
            bk_[nt][0] = __float_as_uint(Ks[(k0 + t) * KSTR + cc]);
            bk_[nt][1] = __float_as_uint(Ks[(k0 + t + 4) * KSTR + cc]);
            bt[nt][0] = __float_as_uint(Ts[(k0 + t) * KSTR + cc]);
            bt[nt][1] = __float_as_uint(Ts[(k0 + t + 4) * KSTR + cc]);
        }
        #pragma unroll
        for (int mt = 0; mt < 2; mt++)
            #pragma unroll
            for (int nt = 0; nt < 2; nt++) {
                mma8(sacc[mt][nt], a[mt], bk_[nt]);
                mma8(iacc[mt][nt], a[mt], bt[nt]);
            }
    }

    #pragma unroll
    for (int mt = 0; mt < 2; mt++) {
        #pragma unroll
        for (int nt = 0; nt < 2; nt++) {
            int r0 = wi + mt * 16 + g;
            int c0 = wj + nt * 8 + 2 * t;
            #pragma unroll
            for (int e = 0; e < 4; e++) {
                int r = r0 + (e >> 1) * 8;
                int cc = c0 + (e & 1);
                float wgt = (r >= cc) ? gn[r] : 0.f;
                Ss[r * QSTR + cc] = f2tf(sacc[mt][nt][e] * wgt);
            }
        }
    }
    __syncthreads();

    float oacc[2][2][4];
    #pragma unroll
    for (int i = 0; i < 2; i++)
        #pragma unroll
        for (int j = 0; j < 2; j++)
            #pragma unroll
            for (int q = 0; q < 4; q++) oacc[i][j][q] = 0.f;

    #pragma unroll
    for (int m8 = 0; m8 < 8; m8++) {
        int k0 = m8 * 8;
        unsigned a[2][4], bf[2][2];
        #pragma unroll
        for (int mt = 0; mt < 2; mt++) {
            int r = wi + mt * 16;
            a[mt][0] = __float_as_uint(Ss[(r + g) * QSTR + k0 + t]);
            a[mt][1] = __float_as_uint(Ss[(r + 8 + g) * QSTR + k0 + t]);
            a[mt][2] = __float_as_uint(Ss[(r + g) * QSTR + k0 + t + 4]);
            a[mt][3] = __float_as_uint(Ss[(r + 8 + g) * QSTR + k0 + t + 4]);
        }
        #pragma unroll
        for (int nt = 0; nt < 2; nt++) {
            int cc = wj + nt * 8 + g;
            bf[nt][0] = __float_as_uint(Vd[(k0 + t) * KSTR + cc]);
            bf[nt][1] = __float_as_uint(Vd[(k0 + t + 4) * KSTR + cc]);
        }
        #pragma unroll
        for (int mt = 0; mt < 2; mt++)
            #pragma unroll
            for (int nt = 0; nt < 2; nt++)
                mma8(oacc[mt][nt], a[mt], bf[nt]);
    }
    __syncthreads();

    #pragma unroll
    for (int mt = 0; mt < 2; mt++) {
        #pragma unroll
        for (int nt = 0; nt < 2; nt++) {
            int r0 = wi + mt * 16 + g;
            int c0 = wj + nt * 8 + 2 * t;
            float scA = gp[r0];
            float scB = gp[r0 + 8];
            Ss[r0 * QSTR + c0]           = oacc[mt][nt][0] + scA * iacc[mt][nt][0];
            Ss[r0 * QSTR + c0 + 1]       = oacc[mt][nt][1] + scA * iacc[mt][nt][1];
            Ss[(r0 + 8) * QSTR + c0]     = oacc[mt][nt][2] + scB * iacc[mt][nt][2];
            Ss[(r0 + 8) * QSTR + c0 + 1] = oacc[mt][nt][3] + scB * iacc[mt][nt][3];
        }
    }
    __syncthreads();

    // GroupNorm + SiLU gate; store Y as fp16 for the output GEMM
    int tok = tid >> 2, sub = tid & 3;
    float vals[16];
    float s = 0.f, sq = 0.f;
    #pragma unroll
    for (int u = 0; u < 16; u++) {
        float v = Ss[tok * QSTR + sub * 16 + u];
        vals[u] = v; s += v; sq += v * v;
    }
    s  += __shfl_xor_sync(0xffffffffu, s, 1);
    s  += __shfl_xor_sync(0xffffffffu, s, 2);
    sq += __shfl_xor_sync(0xffffffffu, sq, 1);
    sq += __shfl_xor_sync(0xffffffffu, sq, 2);
    float mean = s * (1.f / 64.f);
    float inv = rsqrtf(sq * (1.f / 64.f) - mean * mean + 1e-5f);

    size_t row = (size_t)b * TT + (size_t)c * CS + tok;
    int wcol = h * DH + sub * 16;
    const float* gv_ = G + row * DD + wcol;
    __half2* yp = (__half2*)(Y + row * DD + wcol);
    #pragma unroll
    for (int u4 = 0; u4 < 4; u4++) {
        float4 wv = *(const float4*)&gnw[wcol + u4 * 4];
        float4 bv = *(const float4*)&gnb[wcol + u4 * 4];
        float4 gv = *(const float4*)&gv_[u4 * 4];
        float z0, z1, z2, z3;
        z0 = gv.x + (vals[u4*4+0] - mean) * inv * wv.x + bv.x; z0 = z0 / (1.f + expf(-z0));
        z1 = gv.y + (vals[u4*4+1] - mean) * inv * wv.y + bv.y; z1 = z1 / (1.f + expf(-z1));
        z2 = gv.z + (vals[u4*4+2] - mean) * inv * wv.z + bv.z; z2 = z2 / (1.f + expf(-z2));
        z3 = gv.w + (vals[u4*4+3] - mean) * inv * wv.w + bv.w; z3 = z3 / (1.f + expf(-z3));
        yp[u4*2]   = __floats2half2_rn(z0, z1);
        yp[u4*2+1] = __floats2half2_rn(z2, z3);
    }
}

// ============================================================
extern "C" void kernel_launch(void* const* d_in, const int* in_sizes, int n_in,
                              void* d_out, int out_size) {
    const float* x   = (const float*)d_in[0];
    const float* WQ  = (const float*)d_in[1];
    const float* WK  = (const float*)d_in[2];
    const float* WV  = (const float*)d_in[3];
    const float* WG  = (const float*)d_in[4];
    const float* WO  = (const float*)d_in[5];
    const float* gnw = (const float*)d_in[6];
    const float* gnb = (const float*)d_in[7];
    float* out = (float*)d_out;

    __half *Xh, *Wh, *Yh;
    float *Qp, *Kp, *Vp, *Gp, *Bp, *Sp;
    cudaGetSymbolAddress((void**)&Xh, g_Xh);
    cudaGetSymbolAddress((void**)&Wh, g_W5h);
    cudaGetSymbolAddress((void**)&Yh, g_Yh);
    cudaGetSymbolAddress((void**)&Qp, g_Q);
    cudaGetSymbolAddress((void**)&Kp, g_K);
    cudaGetSymbolAddress((void**)&Vp, g_V);
    cudaGetSymbolAddress((void**)&Gp, g_G);
    cudaGetSymbolAddress((void**)&Bp, g_B);
    cudaGetSymbolAddress((void**)&Sp, g_S);

    cudaFuncSetAttribute(proj4_kernel,
                         cudaFuncAttributeMaxDynamicSharedMemorySize, GEMM_SMEM);
    cudaFuncSetAttribute(gemm_kernel,
                         cudaFuncAttributeMaxDynamicSharedMemorySize, GEMM_SMEM);
    cudaFuncSetAttribute(retention_chunk,
                         cudaFuncAttributeMaxDynamicSharedMemorySize, RET_SMEM);

    conv_half<<<dim3(2048, 1, 6), 256>>>(x, WQ, WK, WV, WG, WO, Xh, Wh);

    proj4_kernel<<<dim3(DD / 128, MT / 128, 4), 128, GEMM_SMEM>>>(
        Xh, Wh, Qp, Kp, Vp, Gp);

    chunk_outer<<<dim3(NC, HH, BB), 256>>>(Kp, Vp, Bp);

    scan_state<<<dim3(BB * HH, 16), 256>>>(Bp, Sp);

    retention_chunk<<<dim3(NC, HH, BB), 256, RET_SMEM>>>(Qp, Kp, Vp, Sp,
                                                         Gp, gnw, gnb, Yh);

    gemm_kernel<<<dim3(DD / 128, MT / 128, 1), 128, GEMM_SMEM>>>(
        Yh, Wh + 4 * DD * DD, out);
}

// round 9
// speedup vs baseline: 8.0639x; 1.1027x over previous
#include <cuda_runtime.h>
#include <cuda_fp16.h>
#include <math.h>

#define BB 2
#define TT 2048
#define DD 512
#define HH 8
#define DH 64
#define MT (BB*TT)   // 4096
#define NC 32
#define CS 64

// ---- scratch (static device globals; no allocation) ----
__device__ __half g_Xh[MT*DD];
__device__ __half g_W5h[5*DD*DD];
__device__ __half g_Yh[MT*DD];
__device__ __half g_Qh[MT*DD];
__device__ __half g_Kh[MT*DD];
__device__ __half g_Vh[MT*DD];
__device__ float  g_G[MT*DD];
__device__ float  g_B[BB*HH*NC*DH*DH];
__device__ float  g_S[BB*HH*NC*DH*DH];

// ---- helpers ----
__device__ __forceinline__ void mma16(float* c, const unsigned* a, const unsigned* b) {
    asm volatile("mma.sync.aligned.m16n8k16.row.col.f32.f16.f16.f32 "
        "{%0,%1,%2,%3}, {%4,%5,%6,%7}, {%8,%9}, {%0,%1,%2,%3};\n"
        : "+f"(c[0]), "+f"(c[1]), "+f"(c[2]), "+f"(c[3])
        : "r"(a[0]), "r"(a[1]), "r"(a[2]), "r"(a[3]), "r"(b[0]), "r"(b[1]));
}
__device__ __forceinline__ void ldm4(unsigned* r, unsigned addr) {
    asm volatile("ldmatrix.sync.aligned.m8n8.x4.shared.b16 {%0,%1,%2,%3}, [%4];"
        : "=r"(r[0]), "=r"(r[1]), "=r"(r[2]), "=r"(r[3]) : "r"(addr));
}
__device__ __forceinline__ void ldm4t(unsigned* r, unsigned addr) {
    asm volatile("ldmatrix.sync.aligned.m8n8.x4.trans.shared.b16 {%0,%1,%2,%3}, [%4];"
        : "=r"(r[0]), "=r"(r[1]), "=r"(r[2]), "=r"(r[3]) : "r"(addr));
}
__device__ __forceinline__ void cp16h(__half* smem, const __half* g) {
    unsigned s = (unsigned)__cvta_generic_to_shared(smem);
    asm volatile("cp.async.cg.shared.global [%0], [%1], 16;\n" :: "r"(s), "l"(g));
}
#define CP_COMMIT() asm volatile("cp.async.commit_group;\n" ::: "memory")
#define CP_WAIT1()  asm volatile("cp.async.wait_group 1;\n" ::: "memory")

// ============================================================
// fp16 pre-conversion of x and the five weights.
// ============================================================
__global__ __launch_bounds__(256) void conv_half(
    const float* __restrict__ x,
    const float* __restrict__ w0, const float* __restrict__ w1,
    const float* __restrict__ w2, const float* __restrict__ w3,
    const float* __restrict__ w4,
    __half* __restrict__ xo, __half* __restrict__ wo)
{
    int z = blockIdx.z;
    if (z == 0) {
        int i = blockIdx.x * 256 + threadIdx.x;
        float4 v = ((const float4*)x)[i];
        __half2* d = (__half2*)xo;
        d[2*i]   = __floats2half2_rn(v.x, v.y);
        d[2*i+1] = __floats2half2_rn(v.z, v.w);
    } else {
        if (blockIdx.x >= 256) return;
        const float* s = (z==1)?w0:(z==2)?w1:(z==3)?w2:(z==4)?w3:w4;
        __half2* d = (__half2*)(wo + (size_t)(z-1) * DD * DD);
        int i = blockIdx.x * 256 + threadIdx.x;
        float4 v = ((const float4*)s)[i];
        d[2*i]   = __floats2half2_rn(v.x, v.y);
        d[2*i+1] = __floats2half2_rn(v.z, v.w);
    }
}

// ============================================================
// fp16 GEMM: C = alpha * A @ B (fp32 accum). Output fp32 or fp16.
// CTA 128x128, 4 warps of 64x64, BK=32, 3-stage cp.async.
// ============================================================
#define AS 40
#define BSX 136
#define HAS (128*AS)
#define HBS (32*BSX)
#define GEMM_SMEM (3*(HAS+HBS)*2)

__device__ __forceinline__ void gemm_body_h(const __half* __restrict__ A,
                                            const __half* __restrict__ B,
                                            float* __restrict__ C,
                                            __half* __restrict__ Ch,
                                            int M, int N, int K, float alpha)
{
    extern __shared__ __half smh[];
    __half* Asm = smh;
    __half* Bsm = smh + 3*HAS;

    int tid = threadIdx.x;
    int w = tid >> 5, lane = tid & 31;
    int g = lane >> 2, t = lane & 3;
    int wm = (w >> 1) * 64;
    int wn = (w & 1) * 64;
    int bm = blockIdx.y * 128, bn = blockIdx.x * 128;

    int ar = tid;
    int bkr = tid >> 2, bq = (tid & 3) * 32;

    const __half* Ag = A + (size_t)(bm + ar) * K;
    const __half* Bg = B + (size_t)bkr * N + bn + bq;

    float acc[4][8][4];
    #pragma unroll
    for (int i = 0; i < 4; i++)
        #pragma unroll
        for (int j = 0; j < 8; j++)
            #pragma unroll
            for (int q = 0; q < 4; q++) acc[i][j][q] = 0.f;

    int ntile = K >> 5;

    #pragma unroll
    for (int p = 0; p < 2; p++) {
        #pragma unroll
        for (int i = 0; i < 4; i++) {
            cp16h(&Asm[p*HAS + ar*AS + 8*i], Ag + p*32 + 8*i);
            cp16h(&Bsm[p*HBS + bkr*BSX + bq + 8*i], Bg + (size_t)(p*32) * N + 8*i);
        }
        CP_COMMIT();
    }

    int lrow = lane & 15, lcol = (lane >> 4) << 3;

    for (int kt = 0; kt < ntile; kt++) {
        int cur = kt % 3;
        CP_WAIT1();
        __syncthreads();

        if (kt + 2 < ntile) {
            int s = (kt + 2) % 3;
            int off = (kt + 2) * 32;
            #pragma unroll
            for (int i = 0; i < 4; i++) {
                cp16h(&Asm[s*HAS + ar*AS + 8*i], Ag + off + 8*i);
                cp16h(&Bsm[s*HBS + bkr*BSX + bq + 8*i], Bg + (size_t)off * N + 8*i);
            }
        }
        CP_COMMIT();

        unsigned abase = (unsigned)__cvta_generic_to_shared(Asm + cur*HAS)
                       + ((wm + lrow) * AS + lcol) * 2;
        unsigned bbase = (unsigned)__cvta_generic_to_shared(Bsm + cur*HBS)
                       + (lrow * BSX + wn + lcol) * 2;

        #pragma unroll
        for (int ks = 0; ks < 2; ks++) {
            int k0 = ks * 16;
            unsigned a[4][4], bf[4][4];
            #pragma unroll
            for (int mt = 0; mt < 4; mt++)
                ldm4(a[mt], abase + (mt*16*AS + k0) * 2);
            #pragma unroll
            for (int n2 = 0; n2 < 4; n2++)
                ldm4t(bf[n2], bbase + (k0*BSX + n2*16) * 2);
            #pragma unroll
            for (int mt = 0; mt < 4; mt++)
                #pragma unroll
                for (int nt = 0; nt < 8; nt++)
                    mma16(acc[mt][nt], a[mt], &bf[nt >> 1][(nt & 1) * 2]);
        }
    }

    #pragma unroll
    for (int mt = 0; mt < 4; mt++)
        #pragma unroll
        for (int nt = 0; nt < 8; nt++) {
            int r = bm + wm + mt * 16 + g;
            int c = bn + wn + nt * 8 + 2 * t;
            if (Ch) {
                ((__half2*)&Ch[(size_t)r * N + c])[0] =
                    __floats2half2_rn(alpha * acc[mt][nt][0], alpha * acc[mt][nt][1]);
                ((__half2*)&Ch[(size_t)(r + 8) * N + c])[0] =
                    __floats2half2_rn(alpha * acc[mt][nt][2], alpha * acc[mt][nt][3]);
            } else {
                *(float2*)&C[(size_t)r * N + c] =
                    make_float2(alpha * acc[mt][nt][0], alpha * acc[mt][nt][1]);
                *(float2*)&C[(size_t)(r + 8) * N + c] =
                    make_float2(alpha * acc[mt][nt][2], alpha * acc[mt][nt][3]);
            }
        }
}

__global__ __launch_bounds__(128, 2) void proj4_kernel(const __half* __restrict__ x,
    const __half* __restrict__ W, __half* Qo, __half* Ko, __half* Vo, float* Go)
{
    const __half* Bp; __half* Cph = nullptr; float* Cpf = nullptr; float alpha = 1.f;
    switch (blockIdx.z) {
        case 0:  Bp = W;           Cph = Qo; alpha = 0.125f; break;
        case 1:  Bp = W + DD*DD;   Cph = Ko; break;
        case 2:  Bp = W + 2*DD*DD; Cph = Vo; break;
        default: Bp = W + 3*DD*DD; Cpf = Go; break;
    }
    gemm_body_h(x, Bp, Cpf, Cph, MT, DD, DD, alpha);
}

__global__ __launch_bounds__(128, 2) void gemm_kernel(const __half* __restrict__ A,
                                                      const __half* __restrict__ B,
                                                      float* __restrict__ C)
{
    gemm_body_h(A, B, C, nullptr, MT, DD, DD, 1.f);
}

// ============================================================
// Chunkwise retention — fp16 mma path. Tile stride 72 halves.
// ============================================================
#define TST 72

// K1: B_c[d][e] = sum_j K[j][d] * (gamma^(C-j) V[j][e])
__global__ __launch_bounds__(256) void chunk_outer(const __half* __restrict__ K,
                                                   const __half* __restrict__ V,
                                                   float* __restrict__ Bout)
{
    __shared__ __align__(16) __half Ksm[64*TST];   // [j][d]
    __shared__ __align__(16) __half Vd[64*TST];    // [j][e] decayed

    int c = blockIdx.x, h = blockIdx.y, b = blockIdx.z;
    int tid = threadIdx.x;
    int w = tid >> 5, lane = tid & 31;
    int g = lane >> 2, t = lane & 3;
    int wi = (w >> 2) * 32, wj = (w & 3) * 16;

    float log2g = log2f(1.f - exp2f(-5.f - (float)h));

    int lr = tid >> 2, lc8 = (tid & 3) * 16;
    const __half* Kb = K + ((size_t)b * TT + (size_t)c * CS) * DD + h * DH;
    const __half* Vb = V + ((size_t)b * TT + (size_t)c * CS) * DD + h * DH;
    __half2 dec2 = __float2half2_rn(exp2f(log2g * (float)(CS - lr)));

    *(float4*)&Ksm[lr*TST + lc8]     = *(const float4*)&Kb[(size_t)lr * DD + lc8];
    *(float4*)&Ksm[lr*TST + lc8 + 8] = *(const float4*)&Kb[(size_t)lr * DD + lc8 + 8];
    #pragma unroll
    for (int u = 0; u < 8; u++) {
        __half2 v = *(const __half2*)&Vb[(size_t)lr * DD + lc8 + 2*u];
        *(__half2*)&Vd[lr*TST + lc8 + 2*u] = __hmul2(v, dec2);
    }
    __syncthreads();

    float bacc[2][2][4];
    #pragma unroll
    for (int i = 0; i < 2; i++)
        #pragma unroll
        for (int j = 0; j < 2; j++)
            #pragma unroll
            for (int q = 0; q < 4; q++) bacc[i][j][q] = 0.f;

    unsigned kbase = (unsigned)__cvta_generic_to_shared(Ksm);
    unsigned vbase = (unsigned)__cvta_generic_to_shared(Vd);
    int lrow = lane & 15, lcol = (lane >> 4) << 3;
    int jrow = (lane & 7) | ((lane >> 4) << 3);
    int dcol = ((lane >> 3) & 1) << 3;

    #pragma unroll
    for (int ks = 0; ks < 4; ks++) {
        int j0 = ks * 16;
        unsigned a[2][4], bv[4];
        // A = K^T fragments via trans-ldmatrix on Ksm[j][d]
        #pragma unroll
        for (int mt = 0; mt < 2; mt++)
            ldm4t(a[mt], kbase + ((j0 + jrow)*TST + wi + mt*16 + dcol) * 2);
        // B = Vd[j][e] via trans-ldmatrix ([k][n] row-major)
        ldm4t(bv, vbase + ((j0 + lrow)*TST + wj + lcol) * 2);
        #pragma unroll
        for (int mt = 0; mt < 2; mt++)
            #pragma unroll
            for (int nt = 0; nt < 2; nt++)
                mma16(bacc[mt][nt], a[mt], &bv[2*nt]);
    }

    size_t base = (((size_t)(b * HH + h)) * NC + c) * (DH * DH);
    #pragma unroll
    for (int mt = 0; mt < 2; mt++)
        #pragma unroll
        for (int nt = 0; nt < 2; nt++) {
            int r = wi + mt * 16 + g;
            int cc = wj + nt * 8 + 2 * t;
            *(float2*)&Bout[base + r * DH + cc] = make_float2(bacc[mt][nt][0], bacc[mt][nt][1]);
            *(float2*)&Bout[base + (r + 8) * DH + cc] = make_float2(bacc[mt][nt][2], bacc[mt][nt][3]);
        }
}

// K2a: scan over chunks — batched loads, register prefix.
__global__ __launch_bounds__(256) void scan_state(const float* __restrict__ Bm,
                                                  float* __restrict__ Sm)
{
    int bh = blockIdx.x;
    int h = bh & 7;
    float log2g = log2f(1.f - exp2f(-5.f - (float)h));
    float gc = exp2f(64.f * log2g);

    int e = blockIdx.y * 256 + threadIdx.x;
    size_t base = (size_t)bh * NC * (DH * DH) + e;

    float v[NC];
    #pragma unroll
    for (int c = 0; c < NC; c++) v[c] = Bm[base + (size_t)c * (DH * DH)];
    float s = 0.f;
    #pragma unroll
    for (int c = 0; c < NC; c++) {
        Sm[base + (size_t)c * (DH * DH)] = s;
        s = gc * s + v[c];
    }
}

// K2b: intra + inter + GroupNorm + SiLU gate, all fp16 mma.
__global__ __launch_bounds__(256) void retention_chunk(
    const __half* __restrict__ Q, const __half* __restrict__ K,
    const __half* __restrict__ V, const float* __restrict__ Sm,
    const float* __restrict__ G, const float* __restrict__ gnw,
    const float* __restrict__ gnb, __half* __restrict__ Y)
{
    __shared__ __align__(16) char smb[46608];
    __half* Qh = (__half*)smb;                  // [i][d]
    __half* Kh = (__half*)(smb + 9216);         // [j][d]
    __half* Vh = (__half*)(smb + 18432);        // [j][e] decayed
    __half* Th = (__half*)(smb + 27648);        // [d][e] state
    __half* Sh = (__half*)(smb + 36864);        // [i][j]
    float* gp  = (float*)(smb + 46080);         // gamma^i, 0..64
    float* gn_ = (float*)(smb + 46340);         // gamma^(i-64), 0..63
    float* Os  = (float*)smb;                   // overlay Qh+Kh (after phase 1)

    int c = blockIdx.x, h = blockIdx.y, b = blockIdx.z;
    int tid = threadIdx.x;
    int w = tid >> 5, lane = tid & 31;
    int g = lane >> 2, t = lane & 3;
    int wi = (w >> 2) * 32, wj = (w & 3) * 16;

    float log2g = log2f(1.f - exp2f(-5.f - (float)h));
    if (tid < 65) gp[tid] = exp2f(log2g * (float)tid);
    if (tid < 64) gn_[tid] = exp2f(log2g * (float)(tid - 64));

    int lr = tid >> 2, lc8 = (tid & 3) * 16;
    size_t rowbase = ((size_t)b * TT + (size_t)c * CS + lr) * DD + h * DH;
    const __half* Qb = Q + rowbase;
    const __half* Kb = K + rowbase;
    const __half* Vb = V + rowbase;
    const float* Tb = Sm + (((size_t)(b * HH + h)) * NC + c) * (DH * DH);
    __half2 dec2 = __float2half2_rn(exp2f(log2g * (float)(CS - lr)));

    *(float4*)&Qh[lr*TST + lc8]     = *(const float4*)&Qb[lc8];
    *(float4*)&Qh[lr*TST + lc8 + 8] = *(const float4*)&Qb[lc8 + 8];
    *(float4*)&Kh[lr*TST + lc8]     = *(const float4*)&Kb[lc8];
    *(float4*)&Kh[lr*TST + lc8 + 8] = *(const float4*)&Kb[lc8 + 8];
    #pragma unroll
    for (int u = 0; u < 8; u++) {
        __half2 v = *(const __half2*)&Vb[lc8 + 2*u];
        *(__half2*)&Vh[lr*TST + lc8 + 2*u] = __hmul2(v, dec2);
    }
    #pragma unroll
    for (int u4 = 0; u4 < 4; u4++) {
        float4 tv = *(const float4*)&Tb[lr * DH + lc8 + 4*u4];
        *(__half2*)&Th[lr*TST + lc8 + 4*u4]     = __floats2half2_rn(tv.x, tv.y);
        *(__half2*)&Th[lr*TST + lc8 + 4*u4 + 2] = __floats2half2_rn(tv.z, tv.w);
    }
    __syncthreads();

    unsigned qbase = (unsigned)__cvta_generic_to_shared(Qh);
    unsigned kbase = (unsigned)__cvta_generic_to_shared(Kh);
    unsigned vbase = (unsigned)__cvta_generic_to_shared(Vh);
    unsigned tbase = (unsigned)__cvta_generic_to_shared(Th);
    unsigned sbase = (unsigned)__cvta_generic_to_shared(Sh);
    int lrow = lane & 15, lcol = (lane >> 4) << 3;
    int nrow = (lane & 7) | ((lane >> 4) << 3);
    int kc = ((lane >> 3) & 1) << 3;

    // ---- phase 1: sacc = Q@K^T, iacc = Q@State ----
    float sacc[2][2][4], iacc[2][2][4];
    #pragma unroll
    for (int i = 0; i < 2; i++)
        #pragma unroll
        for (int j = 0; j < 2; j++)
            #pragma unroll
            for (int q = 0; q < 4; q++) { sacc[i][j][q] = 0.f; iacc[i][j][q] = 0.f; }

    #pragma unroll
    for (int ks = 0; ks < 4; ks++) {
        int k0 = ks * 16;
        unsigned a[2][4], bk[4], bt[4];
        #pragma unroll
        for (int mt = 0; mt < 2; mt++)
            ldm4(a[mt], qbase + ((wi + mt*16 + lrow)*TST + k0 + lcol) * 2);
        // B for QK^T: Kh[n=j][k=d] row-major -> non-trans with (n-row, k-half) group map
        ldm4(bk, kbase + ((wj + nrow)*TST + k0 + kc) * 2);
        // B for Q@State: Th[k=d][n=e] row-major -> trans
        ldm4t(bt, tbase + ((k0 + lrow)*TST + wj + lcol) * 2);
        #pragma unroll
        for (int mt = 0; mt < 2; mt++)
            #pragma unroll
            for (int nt = 0; nt < 2; nt++) {
                mma16(sacc[mt][nt], a[mt], &bk[2*nt]);
                mma16(iacc[mt][nt], a[mt], &bt[2*nt]);
            }
    }

    // decay-mask S (gamma^(i-64); pairs with gamma^(64-j) folded into Vh)
    #pragma unroll
    for (int mt = 0; mt < 2; mt++) {
        #pragma unroll
        for (int nt = 0; nt < 2; nt++) {
            int r0 = wi + mt * 16 + g;
            int c0 = wj + nt * 8 + 2 * t;
            float w0 = gn_[r0], w1 = gn_[r0 + 8];
            float m00 = (r0 >= c0) ? w0 : 0.f;
            float m01 = (r0 >= c0 + 1) ? w0 : 0.f;
            float m10 = (r0 + 8 >= c0) ? w1 : 0.f;
            float m11 = (r0 + 8 >= c0 + 1) ? w1 : 0.f;
            *(__half2*)&Sh[r0*TST + c0] =
                __floats2half2_rn(sacc[mt][nt][0]*m00, sacc[mt][nt][1]*m01);
            *(__half2*)&Sh[(r0+8)*TST + c0] =
                __floats2half2_rn(sacc[mt][nt][2]*m10, sacc[mt][nt][3]*m11);
        }
    }
    __syncthreads();

    // ---- phase 2: O_intra = S @ Vd ----
    float oacc[2][2][4];
    #pragma unroll
    for (int i = 0; i < 2; i++)
        #pragma unroll
        for (int j = 0; j < 2; j++)
            #pragma unroll
            for (int q = 0; q < 4; q++) oacc[i][j][q] = 0.f;

    #pragma unroll
    for (int ks = 0; ks < 4; ks++) {
        int k0 = ks * 16;
        unsigned a[2][4], bv[4];
        #pragma unroll
        for (int mt = 0; mt < 2; mt++)
            ldm4(a[mt], sbase + ((wi + mt*16 + lrow)*TST + k0 + lcol) * 2);
        ldm4t(bv, vbase + ((k0 + lrow)*TST + wj + lcol) * 2);
        #pragma unroll
        for (int mt = 0; mt < 2; mt++)
            #pragma unroll
            for (int nt = 0; nt < 2; nt++)
                mma16(oacc[mt][nt], a[mt], &bv[2*nt]);
    }

    // combine intra + gamma^i * inter into Os (overlays Qh/Kh; their reads
    // finished before the pre-phase-2 barrier)
    #pragma unroll
    for (int mt = 0; mt < 2; mt++) {
        #pragma unroll
        for (int nt = 0; nt < 2; nt++) {
            int r0 = wi + mt * 16 + g;
            int c0 = wj + nt * 8 + 2 * t;
            float scA = gp[r0], scB = gp[r0 + 8];
            *(float2*)&Os[r0*68 + c0] = make_float2(
                oacc[mt][nt][0] + scA * iacc[mt][nt][0],
                oacc[mt][nt][1] + scA * iacc[mt][nt][1]);
            *(float2*)&Os[(r0+8)*68 + c0] = make_float2(
                oacc[mt][nt][2] + scB * iacc[mt][nt][2],
                oacc[mt][nt][3] + scB * iacc[mt][nt][3]);
        }
    }
    __syncthreads();

    // ---- GroupNorm + SiLU gate; Y stored fp16 for the output GEMM ----
    int tok = tid >> 2, sub = tid & 3;
    float vals[16];
    float s = 0.f, sq = 0.f;
    #pragma unroll
    for (int u = 0; u < 16; u++) {
        float v = Os[tok * 68 + sub * 16 + u];
        vals[u] = v; s += v; sq += v * v;
    }
    s  += __shfl_xor_sync(0xffffffffu, s, 1);
    s  += __shfl_xor_sync(0xffffffffu, s, 2);
    sq += __shfl_xor_sync(0xffffffffu, sq, 1);
    sq += __shfl_xor_sync(0xffffffffu, sq, 2);
    float mean = s * (1.f / 64.f);
    float inv = rsqrtf(sq * (1.f / 64.f) - mean * mean + 1e-5f);

    size_t row = (size_t)b * TT + (size_t)c * CS + tok;
    int wcol = h * DH + sub * 16;
    const float* gv_ = G + row * DD + wcol;
    __half2* yp = (__half2*)(Y + row * DD + wcol);
    #pragma unroll
    for (int u4 = 0; u4 < 4; u4++) {
        float4 wv = *(const float4*)&gnw[wcol + u4 * 4];
        float4 bv = *(const float4*)&gnb[wcol + u4 * 4];
        float4 gv = *(const float4*)&gv_[u4 * 4];
        float z0, z1, z2, z3;
        z0 = gv.x + (vals[u4*4+0] - mean) * inv * wv.x + bv.x; z0 = z0 / (1.f + expf(-z0));
        z1 = gv.y + (vals[u4*4+1] - mean) * inv * wv.y + bv.y; z1 = z1 / (1.f + expf(-z1));
        z2 = gv.z + (vals[u4*4+2] - mean) * inv * wv.z + bv.z; z2 = z2 / (1.f + expf(-z2));
        z3 = gv.w + (vals[u4*4+3] - mean) * inv * wv.w + bv.w; z3 = z3 / (1.f + expf(-z3));
        yp[u4*2]   = __floats2half2_rn(z0, z1);
        yp[u4*2+1] = __floats2half2_rn(z2, z3);
    }
}

// ============================================================
extern "C" void kernel_launch(void* const* d_in, const int* in_sizes, int n_in,
                              void* d_out, int out_size) {
    const float* x   = (const float*)d_in[0];
    const float* WQ  = (const float*)d_in[1];
    const float* WK  = (const float*)d_in[2];
    const float* WV  = (const float*)d_in[3];
    const float* WG  = (const float*)d_in[4];
    const float* WO  = (const float*)d_in[5];
    const float* gnw = (const float*)d_in[6];
    const float* gnb = (const float*)d_in[7];
    float* out = (float*)d_out;

    __half *Xh, *Wh, *Yh, *Qh, *Kh, *Vh;
    float *Gp, *Bp, *Sp;
    cudaGetSymbolAddress((void**)&Xh, g_Xh);
    cudaGetSymbolAddress((void**)&Wh, g_W5h);
    cudaGetSymbolAddress((void**)&Yh, g_Yh);
    cudaGetSymbolAddress((void**)&Qh, g_Qh);
    cudaGetSymbolAddress((void**)&Kh, g_Kh);
    cudaGetSymbolAddress((void**)&Vh, g_Vh);
    cudaGetSymbolAddress((void**)&Gp, g_G);
    cudaGetSymbolAddress((void**)&Bp, g_B);
    cudaGetSymbolAddress((void**)&Sp, g_S);

    cudaFuncSetAttribute(proj4_kernel,
                         cudaFuncAttributeMaxDynamicSharedMemorySize, GEMM_SMEM);
    cudaFuncSetAttribute(gemm_kernel,
                         cudaFuncAttributeMaxDynamicSharedMemorySize, GEMM_SMEM);

    conv_half<<<dim3(2048, 1, 6), 256>>>(x, WQ, WK, WV, WG, WO, Xh, Wh);

    proj4_kernel<<<dim3(DD / 128, MT / 128, 4), 128, GEMM_SMEM>>>(
        Xh, Wh, Qh, Kh, Vh, Gp);

    chunk_outer<<<dim3(NC, HH, BB), 256>>>(Kh, Vh, Bp);

    scan_state<<<dim3(BB * HH, 16), 256>>>(Bp, Sp);

    retention_chunk<<<dim3(NC, HH, BB), 256>>>(Qh, Kh, Vh, Sp,
                                               Gp, gnw, gnb, Yh);

    gemm_kernel<<<dim3(DD / 128, MT / 128, 1), 128, GEMM_SMEM>>>(
        Yh, Wh + 4 * DD * DD, out);
}

// round 11
// speedup vs baseline: 8.2034x; 1.0173x over previous
#include <cuda_runtime.h>
#include <cuda_fp16.h>
#include <math.h>

#define BB 2
#define TT 2048
#define DD 512
#define HH 8
#define DH 64
#define MT (BB*TT)   // 4096
#define NC 32
#define CS 64

// ---- scratch (static device globals; no allocation) ----
__device__ __half g_Xh[MT*DD];
__device__ __half g_W5h[5*DD*DD];
__device__ __half g_Yh[MT*DD];
__device__ __half g_Qh[MT*DD];
__device__ __half g_Kh[MT*DD];
__device__ __half g_Vh[MT*DD];
__device__ __half g_Gh[MT*DD];
__device__ float  g_B[BB*HH*NC*DH*DH];
__device__ float  g_S[BB*HH*NC*DH*DH];

// ---- helpers ----
__device__ __forceinline__ void mma16(float* c, const unsigned* a, const unsigned* b) {
    asm volatile("mma.sync.aligned.m16n8k16.row.col.f32.f16.f16.f32 "
        "{%0,%1,%2,%3}, {%4,%5,%6,%7}, {%8,%9}, {%0,%1,%2,%3};\n"
        : "+f"(c[0]), "+f"(c[1]), "+f"(c[2]), "+f"(c[3])
        : "r"(a[0]), "r"(a[1]), "r"(a[2]), "r"(a[3]), "r"(b[0]), "r"(b[1]));
}
__device__ __forceinline__ void ldm4(unsigned* r, unsigned addr) {
    asm volatile("ldmatrix.sync.aligned.m8n8.x4.shared.b16 {%0,%1,%2,%3}, [%4];"
        : "=r"(r[0]), "=r"(r[1]), "=r"(r[2]), "=r"(r[3]) : "r"(addr));
}
__device__ __forceinline__ void ldm4t(unsigned* r, unsigned addr) {
    asm volatile("ldmatrix.sync.aligned.m8n8.x4.trans.shared.b16 {%0,%1,%2,%3}, [%4];"
        : "=r"(r[0]), "=r"(r[1]), "=r"(r[2]), "=r"(r[3]) : "r"(addr));
}
__device__ __forceinline__ void cp16h(__half* smem, const __half* g) {
    unsigned s = (unsigned)__cvta_generic_to_shared(smem);
    asm volatile("cp.async.cg.shared.global [%0], [%1], 16;\n" :: "r"(s), "l"(g));
}
#define CP_COMMIT() asm volatile("cp.async.commit_group;\n" ::: "memory")
#define CP_WAIT1()  asm volatile("cp.async.wait_group 1;\n" ::: "memory")

// ============================================================
// fp16 pre-conversion of x and the five weights.
// ============================================================
__global__ __launch_bounds__(256) void conv_half(
    const float* __restrict__ x,
    const float* __restrict__ w0, const float* __restrict__ w1,
    const float* __restrict__ w2, const float* __restrict__ w3,
    const float* __restrict__ w4,
    __half* __restrict__ xo, __half* __restrict__ wo)
{
    int z = blockIdx.z;
    if (z == 0) {
        int i = blockIdx.x * 256 + threadIdx.x;
        float4 v = ((const float4*)x)[i];
        __half2* d = (__half2*)xo;
        d[2*i]   = __floats2half2_rn(v.x, v.y);
        d[2*i+1] = __floats2half2_rn(v.z, v.w);
    } else {
        if (blockIdx.x >= 256) return;
        const float* s = (z==1)?w0:(z==2)?w1:(z==3)?w2:(z==4)?w3:w4;
        __half2* d = (__half2*)(wo + (size_t)(z-1) * DD * DD);
        int i = blockIdx.x * 256 + threadIdx.x;
        float4 v = ((const float4*)s)[i];
        d[2*i]   = __floats2half2_rn(v.x, v.y);
        d[2*i+1] = __floats2half2_rn(v.z, v.w);
    }
}

// ============================================================
// fp16 GEMM: C = alpha * A @ B (fp32 accum). Output fp32 or fp16.
// Template MTILES: 4 -> CTA tile 128x128, 2 -> CTA tile 64x128.
// 4 warps, warp tile (MTILES*16)x64, BK=32, 3-stage cp.async.
// ============================================================
#define HBSz (32*136)
#define SM4 (3*(128*40 + HBSz)*2)   // 56832
#define SM2 (3*(64*40 + HBSz)*2)    // 41472

template<int MTILES>
__device__ __forceinline__ void gemm_body_h(const __half* __restrict__ A,
                                            const __half* __restrict__ B,
                                            float* __restrict__ Cf,
                                            __half* __restrict__ Ch,
                                            float alpha)
{
    constexpr int BM = MTILES * 32;
    constexpr int HASz = BM * 40;

    extern __shared__ __half smh[];
    __half* Asm = smh;
    __half* Bsm = smh + 3*HASz;

    int tid = threadIdx.x;
    int w = tid >> 5, lane = tid & 31;
    int g = lane >> 2, t = lane & 3;
    int wm = (w >> 1) * (MTILES * 16);
    int wn = (w & 1) * 64;
    int bm = blockIdx.y * BM, bn = blockIdx.x * 128;

    int bkr = tid >> 2, bq = (tid & 3) * 32;
    const __half* Bg = B + (size_t)bkr * DD + bn + bq;

    float acc[MTILES][8][4];
    #pragma unroll
    for (int i = 0; i < MTILES; i++)
        #pragma unroll
        for (int j = 0; j < 8; j++)
            #pragma unroll
            for (int q = 0; q < 4; q++) acc[i][j][q] = 0.f;

    auto load_chunk = [&](int kt, int s) {
        int off = kt * 32;
        if (MTILES == 4) {
            const __half* Ag = A + (size_t)(bm + tid) * DD + off;
            #pragma unroll
            for (int i = 0; i < 4; i++)
                cp16h(&Asm[s*HASz + tid*40 + 8*i], Ag + 8*i);
        } else {
            #pragma unroll
            for (int i = 0; i < 2; i++) {
                int o = i * 128 + tid;
                int row = o >> 2, sg = (o & 3) * 8;
                cp16h(&Asm[s*HASz + row*40 + sg],
                      A + (size_t)(bm + row) * DD + off + sg);
            }
        }
        #pragma unroll
        for (int i = 0; i < 4; i++)
            cp16h(&Bsm[s*HBSz + bkr*136 + bq + 8*i], Bg + (size_t)off * DD + 8*i);
    };

    load_chunk(0, 0); CP_COMMIT();
    load_chunk(1, 1); CP_COMMIT();

    int lrow = lane & 15, lcol = (lane >> 4) << 3;

    #pragma unroll 1
    for (int kt = 0; kt < 16; kt++) {
        int cur = kt % 3;
        CP_WAIT1();
        __syncthreads();

        if (kt + 2 < 16)
            load_chunk(kt + 2, (kt + 2) % 3);
        CP_COMMIT();

        unsigned abase = (unsigned)__cvta_generic_to_shared(Asm + cur*HASz)
                       + ((wm + lrow) * 40 + lcol) * 2;
        unsigned bbase = (unsigned)__cvta_generic_to_shared(Bsm + cur*HBSz)
                       + (lrow * 136 + wn + lcol) * 2;

        #pragma unroll
        for (int ks = 0; ks < 2; ks++) {
            int k0 = ks * 16;
            unsigned a[MTILES][4], bf[4][4];
            #pragma unroll
            for (int mt = 0; mt < MTILES; mt++)
                ldm4(a[mt], abase + (mt*16*40 + k0) * 2);
            #pragma unroll
            for (int n2 = 0; n2 < 4; n2++)
                ldm4t(bf[n2], bbase + (k0*136 + n2*16) * 2);
            #pragma unroll
            for (int mt = 0; mt < MTILES; mt++)
                #pragma unroll
                for (int nt = 0; nt < 8; nt++)
                    mma16(acc[mt][nt], a[mt], &bf[nt >> 1][(nt & 1) * 2]);
        }
    }

    #pragma unroll
    for (int mt = 0; mt < MTILES; mt++)
        #pragma unroll
        for (int nt = 0; nt < 8; nt++) {
            int r = bm + wm + mt * 16 + g;
            int c = bn + wn + nt * 8 + 2 * t;
            if (Ch) {
                ((__half2*)&Ch[(size_t)r * DD + c])[0] =
                    __floats2half2_rn(alpha * acc[mt][nt][0], alpha * acc[mt][nt][1]);
                ((__half2*)&Ch[(size_t)(r + 8) * DD + c])[0] =
                    __floats2half2_rn(alpha * acc[mt][nt][2], alpha * acc[mt][nt][3]);
            } else {
                *(float2*)&Cf[(size_t)r * DD + c] =
                    make_float2(alpha * acc[mt][nt][0], alpha * acc[mt][nt][1]);
                *(float2*)&Cf[(size_t)(r + 8) * DD + c] =
                    make_float2(alpha * acc[mt][nt][2], alpha * acc[mt][nt][3]);
            }
        }
}

__global__ __launch_bounds__(128, 2) void proj4_kernel(const __half* __restrict__ x,
    const __half* __restrict__ W, __half* Qo, __half* Ko, __half* Vo, __half* Go)
{
    const __half* Bp; __half* Cph; float alpha = 1.f;
    switch (blockIdx.z) {
        case 0:  Bp = W;           Cph = Qo; alpha = 0.125f; break;
        case 1:  Bp = W + DD*DD;   Cph = Ko; break;
        case 2:  Bp = W + 2*DD*DD; Cph = Vo; break;
        default: Bp = W + 3*DD*DD; Cph = Go; break;
    }
    gemm_body_h<4>(x, Bp, nullptr, Cph, alpha);
}

__global__ __launch_bounds__(128, 4) void gemm_out(const __half* __restrict__ A,
                                                   const __half* __restrict__ B,
                                                   float* __restrict__ C)
{
    gemm_body_h<2>(A, B, C, nullptr, 1.f);
}

// ============================================================
// Chunkwise retention — fp16 mma path.
// ============================================================
#define TST 72

__global__ __launch_bounds__(256) void chunk_outer(const __half* __restrict__ K,
                                                   const __half* __restrict__ V,
                                                   float* __restrict__ Bout)
{
    __shared__ __align__(16) __half Ksm[64*TST];
    __shared__ __align__(16) __half Vd[64*TST];

    int c = blockIdx.x, h = blockIdx.y, b = blockIdx.z;
    int tid = threadIdx.x;
    int w = tid >> 5, lane = tid & 31;
    int g = lane >> 2, t = lane & 3;
    int wi = (w >> 2) * 32, wj = (w & 3) * 16;

    float log2g = log2f(1.f - exp2f(-5.f - (float)h));

    int lr = tid >> 2, lc8 = (tid & 3) * 16;
    const __half* Kb = K + ((size_t)b * TT + (size_t)c * CS) * DD + h * DH;
    const __half* Vb = V + ((size_t)b * TT + (size_t)c * CS) * DD + h * DH;
    __half2 dec2 = __float2half2_rn(exp2f(log2g * (float)(CS - lr)));

    *(float4*)&Ksm[lr*TST + lc8]     = *(const float4*)&Kb[(size_t)lr * DD + lc8];
    *(float4*)&Ksm[lr*TST + lc8 + 8] = *(const float4*)&Kb[(size_t)lr * DD + lc8 + 8];
    #pragma unroll
    for (int u = 0; u < 8; u++) {
        __half2 v = *(const __half2*)&Vb[(size_t)lr * DD + lc8 + 2*u];
        *(__half2*)&Vd[lr*TST + lc8 + 2*u] = __hmul2(v, dec2);
    }
    __syncthreads();

    float bacc[2][2][4];
    #pragma unroll
    for (int i = 0; i < 2; i++)
        #pragma unroll
        for (int j = 0; j < 2; j++)
            #pragma unroll
            for (int q = 0; q < 4; q++) bacc[i][j][q] = 0.f;

    unsigned kbase = (unsigned)__cvta_generic_to_shared(Ksm);
    unsigned vbase = (unsigned)__cvta_generic_to_shared(Vd);
    int lrow = lane & 15, lcol = (lane >> 4) << 3;
    int jrow = (lane & 7) | ((lane >> 4) << 3);
    int dcol = ((lane >> 3) & 1) << 3;

    #pragma unroll
    for (int ks = 0; ks < 4; ks++) {
        int j0 = ks * 16;
        unsigned a[2][4], bv[4];
        #pragma unroll
        for (int mt = 0; mt < 2; mt++)
            ldm4t(a[mt], kbase + ((j0 + jrow)*TST + wi + mt*16 + dcol) * 2);
        ldm4t(bv, vbase + ((j0 + lrow)*TST + wj + lcol) * 2);
        #pragma unroll
        for (int mt = 0; mt < 2; mt++)
            #pragma unroll
            for (int nt = 0; nt < 2; nt++)
                mma16(bacc[mt][nt], a[mt], &bv[2*nt]);
    }

    size_t base = (((size_t)(b * HH + h)) * NC + c) * (DH * DH);
    #pragma unroll
    for (int mt = 0; mt < 2; mt++)
        #pragma unroll
        for (int nt = 0; nt < 2; nt++) {
            int r = wi + mt * 16 + g;
            int cc = wj + nt * 8 + 2 * t;
            *(float2*)&Bout[base + r * DH + cc] = make_float2(bacc[mt][nt][0], bacc[mt][nt][1]);
            *(float2*)&Bout[base + (r + 8) * DH + cc] = make_float2(bacc[mt][nt][2], bacc[mt][nt][3]);
        }
}

// scan over chunks — 8-wide register batches (no spill)
__global__ __launch_bounds__(256) void scan_state(const float* __restrict__ Bm,
                                                  float* __restrict__ Sm)
{
    int bh = blockIdx.x;
    int h = bh & 7;
    float log2g = log2f(1.f - exp2f(-5.f - (float)h));
    float gc = exp2f(64.f * log2g);

    int e = blockIdx.y * 256 + threadIdx.x;
    size_t base = (size_t)bh * NC * (DH * DH) + e;

    float s = 0.f;
    #pragma unroll
    for (int c0 = 0; c0 < NC; c0 += 8) {
        float v[8];
        #pragma unroll
        for (int j = 0; j < 8; j++) v[j] = Bm[base + (size_t)(c0 + j) * (DH * DH)];
        #pragma unroll
        for (int j = 0; j < 8; j++) {
            Sm[base + (size_t)(c0 + j) * (DH * DH)] = s;
            s = gc * s + v[j];
        }
    }
}

// intra + inter + GroupNorm + SiLU gate, fp16 mma
__global__ __launch_bounds__(256) void retention_chunk(
    const __half* __restrict__ Q, const __half* __restrict__ K,
    const __half* __restrict__ V, const float* __restrict__ Sm,
    const __half* __restrict__ G, const float* __restrict__ gnw,
    const float* __restrict__ gnb, __half* __restrict__ Y)
{
    __shared__ __align__(16) char smb[46608];
    __half* Qh = (__half*)smb;
    __half* Kh = (__half*)(smb + 9216);
    __half* Vh = (__half*)(smb + 18432);
    __half* Th = (__half*)(smb + 27648);
    __half* Sh = (__half*)(smb + 36864);
    float* gp  = (float*)(smb + 46080);
    float* gn_ = (float*)(smb + 46340);
    float* Os  = (float*)smb;

    int c = blockIdx.x, h = blockIdx.y, b = blockIdx.z;
    int tid = threadIdx.x;
    int w = tid >> 5, lane = tid & 31;
    int g = lane >> 2, t = lane & 3;
    int wi = (w >> 2) * 32, wj = (w & 3) * 16;

    float log2g = log2f(1.f - exp2f(-5.f - (float)h));
    if (tid < 65) gp[tid] = exp2f(log2g * (float)tid);
    if (tid < 64) gn_[tid] = exp2f(log2g * (float)(tid - 64));

    int lr = tid >> 2, lc8 = (tid & 3) * 16;
    size_t rowbase = ((size_t)b * TT + (size_t)c * CS + lr) * DD + h * DH;
    const __half* Qb = Q + rowbase;
    const __half* Kb = K + rowbase;
    const __half* Vb = V + rowbase;
    const float* Tb = Sm + (((size_t)(b * HH + h)) * NC + c) * (DH * DH);
    __half2 dec2 = __float2half2_rn(exp2f(log2g * (float)(CS - lr)));

    *(float4*)&Qh[lr*TST + lc8]     = *(const float4*)&Qb[lc8];
    *(float4*)&Qh[lr*TST + lc8 + 8] = *(const float4*)&Qb[lc8 + 8];
    *(float4*)&Kh[lr*TST + lc8]     = *(const float4*)&Kb[lc8];
    *(float4*)&Kh[lr*TST + lc8 + 8] = *(const float4*)&Kb[lc8 + 8];
    #pragma unroll
    for (int u = 0; u < 8; u++) {
        __half2 v = *(const __half2*)&Vb[lc8 + 2*u];
        *(__half2*)&Vh[lr*TST + lc8 + 2*u] = __hmul2(v, dec2);
    }
    #pragma unroll
    for (int u4 = 0; u4 < 4; u4++) {
        float4 tv = *(const float4*)&Tb[lr * DH + lc8 + 4*u4];
        *(__half2*)&Th[lr*TST + lc8 + 4*u4]     = __floats2half2_rn(tv.x, tv.y);
        *(__half2*)&Th[lr*TST + lc8 + 4*u4 + 2] = __floats2half2_rn(tv.z, tv.w);
    }
    __syncthreads();

    unsigned qbase = (unsigned)__cvta_generic_to_shared(Qh);
    unsigned kbase = (unsigned)__cvta_generic_to_shared(Kh);
    unsigned vbase = (unsigned)__cvta_generic_to_shared(Vh);
    unsigned tbase = (unsigned)__cvta_generic_to_shared(Th);
    unsigned sbase2 = (unsigned)__cvta_generic_to_shared(Sh);
    int lrow = lane & 15, lcol = (lane >> 4) << 3;
    int nrow = (lane & 7) | ((lane >> 4) << 3);
    int kc = ((lane >> 3) & 1) << 3;

    float sacc[2][2][4], iacc[2][2][4];
    #pragma unroll
    for (int i = 0; i < 2; i++)
        #pragma unroll
        for (int j = 0; j < 2; j++)
            #pragma unroll
            for (int q = 0; q < 4; q++) { sacc[i][j][q] = 0.f; iacc[i][j][q] = 0.f; }

    #pragma unroll
    for (int ks = 0; ks < 4; ks++) {
        int k0 = ks * 16;
        unsigned a[2][4], bk[4], bt[4];
        #pragma unroll
        for (int mt = 0; mt < 2; mt++)
            ldm4(a[mt], qbase + ((wi + mt*16 + lrow)*TST + k0 + lcol) * 2);
        ldm4(bk, kbase + ((wj + nrow)*TST + k0 + kc) * 2);
        ldm4t(bt, tbase + ((k0 + lrow)*TST + wj + lcol) * 2);
        #pragma unroll
        for (int mt = 0; mt < 2; mt++)
            #pragma unroll
            for (int nt = 0; nt < 2; nt++) {
                mma16(sacc[mt][nt], a[mt], &bk[2*nt]);
                mma16(iacc[mt][nt], a[mt], &bt[2*nt]);
            }
    }

    #pragma unroll
    for (int mt = 0; mt < 2; mt++) {
        #pragma unroll
        for (int nt = 0; nt < 2; nt++) {
            int r0 = wi + mt * 16 + g;
            int c0 = wj + nt * 8 + 2 * t;
            float w0 = gn_[r0], w1 = gn_[r0 + 8];
            float m00 = (r0 >= c0) ? w0 : 0.f;
            float m01 = (r0 >= c0 + 1) ? w0 : 0.f;
            float m10 = (r0 + 8 >= c0) ? w1 : 0.f;
            float m11 = (r0 + 8 >= c0 + 1) ? w1 : 0.f;
            *(__half2*)&Sh[r0*TST + c0] =
                __floats2half2_rn(sacc[mt][nt][0]*m00, sacc[mt][nt][1]*m01);
            *(__half2*)&Sh[(r0+8)*TST + c0] =
                __floats2half2_rn(sacc[mt][nt][2]*m10, sacc[mt][nt][3]*m11);
        }
    }
    __syncthreads();

    float oacc[2][2][4];
    #pragma unroll
    for (int i = 0; i < 2; i++)
        #pragma unroll
        for (int j = 0; j < 2; j++)
            #pragma unroll
            for (int q = 0; q < 4; q++) oacc[i][j][q] = 0.f;

    #pragma unroll
    for (int ks = 0; ks < 4; ks++) {
        int k0 = ks * 16;
        unsigned a[2][4], bv[4];
        #pragma unroll
        for (int mt = 0; mt < 2; mt++)
            ldm4(a[mt], sbase2 + ((wi + mt*16 + lrow)*TST + k0 + lcol) * 2);
        ldm4t(bv, vbase + ((k0 + lrow)*TST + wj + lcol) * 2);
        #pragma unroll
        for (int mt = 0; mt < 2; mt++)
            #pragma unroll
            for (int nt = 0; nt < 2; nt++)
                mma16(oacc[mt][nt], a[mt], &bv[2*nt]);
    }

    #pragma unroll
    for (int mt = 0; mt < 2; mt++) {
        #pragma unroll
        for (int nt = 0; nt < 2; nt++) {
            int r0 = wi + mt * 16 + g;
            int c0 = wj + nt * 8 + 2 * t;
            float scA = gp[r0], scB = gp[r0 + 8];
            *(float2*)&Os[r0*68 + c0] = make_float2(
                oacc[mt][nt][0] + scA * iacc[mt][nt][0],
                oacc[mt][nt][1] + scA * iacc[mt][nt][1]);
            *(float2*)&Os[(r0+8)*68 + c0] = make_float2(
                oacc[mt][nt][2] + scB * iacc[mt][nt][2],
                oacc[mt][nt][3] + scB * iacc[mt][nt][3]);
        }
    }
    __syncthreads();

    int tok = tid >> 2, sub = tid & 3;
    float vals[16];
    float s = 0.f, sq = 0.f;
    #pragma unroll
    for (int u = 0; u < 16; u++) {
        float v = Os[tok * 68 + sub * 16 + u];
        vals[u] = v; s += v; sq += v * v;
    }
    s  += __shfl_xor_sync(0xffffffffu, s, 1);
    s  += __shfl_xor_sync(0xffffffffu, s, 2);
    sq += __shfl_xor_sync(0xffffffffu, sq, 1);
    sq += __shfl_xor_sync(0xffffffffu, sq, 2);
    float mean = s * (1.f / 64.f);
    float inv = rsqrtf(sq * (1.f / 64.f) - mean * mean + 1e-5f);

    size_t row = (size_t)b * TT + (size_t)c * CS + tok;
    int wcol = h * DH + sub * 16;
    const __half2* gh = (const __half2*)(G + row * DD + wcol);
    __half2* yp = (__half2*)(Y + row * DD + wcol);
    #pragma unroll
    for (int u4 = 0; u4 < 4; u4++) {
        float4 wv = *(const float4*)&gnw[wcol + u4 * 4];
        float4 bv = *(const float4*)&gnb[wcol + u4 * 4];
        float2 g0 = __half22float2(gh[u4*2]);
        float2 g1 = __half22float2(gh[u4*2+1]);
        float z0, z1, z2, z3;
        z0 = g0.x + (vals[u4*4+0] - mean) * inv * wv.x + bv.x; z0 = z0 / (1.f + expf(-z0));
        z1 = g0.y + (vals[u4*4+1] - mean) * inv * wv.y + bv.y; z1 = z1 / (1.f + expf(-z1));
        z2 = g1.x + (vals[u4*4+2] - mean) * inv * wv.z + bv.z; z2 = z2 / (1.f + expf(-z2));
        z3 = g1.y + (vals[u4*4+3] - mean) * inv * wv.w + bv.w; z3 = z3 / (1.f + expf(-z3));
        yp[u4*2]   = __floats2half2_rn(z0, z1);
        yp[u4*2+1] = __floats2half2_rn(z2, z3);
    }
}

// ============================================================
extern "C" void kernel_launch(void* const* d_in, const int* in_sizes, int n_in,
                              void* d_out, int out_size) {
    const float* x   = (const float*)d_in[0];
    const float* WQ  = (const float*)d_in[1];
    const float* WK  = (const float*)d_in[2];
    const float* WV  = (const float*)d_in[3];
    const float* WG  = (const float*)d_in[4];
    const float* WO  = (const float*)d_in[5];
    const float* gnw = (const float*)d_in[6];
    const float* gnb = (const float*)d_in[7];
    float* out = (float*)d_out;

    __half *Xh, *Wh, *Yh, *Qh, *Kh, *Vh, *Gh;
    float *Bp, *Sp;
    cudaGetSymbolAddress((void**)&Xh, g_Xh);
    cudaGetSymbolAddress((void**)&Wh, g_W5h);
    cudaGetSymbolAddress((void**)&Yh, g_Yh);
    cudaGetSymbolAddress((void**)&Qh, g_Qh);
    cudaGetSymbolAddress((void**)&Kh, g_Kh);
    cudaGetSymbolAddress((void**)&Vh, g_Vh);
    cudaGetSymbolAddress((void**)&Gh, g_Gh);
    cudaGetSymbolAddress((void**)&Bp, g_B);
    cudaGetSymbolAddress((void**)&Sp, g_S);

    cudaFuncSetAttribute(proj4_kernel,
                         cudaFuncAttributeMaxDynamicSharedMemorySize, SM4);
    cudaFuncSetAttribute(gemm_out,
                         cudaFuncAttributeMaxDynamicSharedMemorySize, SM2);

    conv_half<<<dim3(2048, 1, 6), 256>>>(x, WQ, WK, WV, WG, WO, Xh, Wh);

    proj4_kernel<<<dim3(DD / 128, MT / 128, 4), 128, SM4>>>(
        Xh, Wh, Qh, Kh, Vh, Gh);

    chunk_outer<<<dim3(NC, HH, BB), 256>>>(Kh, Vh, Bp);

    scan_state<<<dim3(BB * HH, 16), 256>>>(Bp, Sp);

    retention_chunk<<<dim3(NC, HH, BB), 256>>>(Qh, Kh, Vh, Sp,
                                               Gh, gnw, gnb, Yh);

    gemm_out<<<dim3(DD / 128, MT / 64), 128, SM2>>>(
        Yh, Wh + 4 * DD * DD, out);
}